// round 13
// baseline (speedup 1.0000x reference)
#include <cuda_runtime.h>
#include <cuda_bf16.h>
#include <math.h>
#include <stdint.h>

// Problem constants
#define SEQ   2048
#define DM    1024
#define NH    16
#define DK    64
#define DFF   4096
#define NL    4
#define LN_EPS 1e-5f

// ---------------------------------------------------------------------------
// Scratch (static device globals: allocation-free kernel_launch)
// ---------------------------------------------------------------------------
__device__ __nv_bfloat16 g_wqkvh[(size_t)NL*DM*3*DM], g_wqkvl[(size_t)NL*DM*3*DM];
__device__ float         g_bqkv[NL*3*DM];
__device__ __nv_bfloat16 g_woh[NL*DM*DM],  g_wol[NL*DM*DM];
__device__ __nv_bfloat16 g_w1h[NL*DM*DFF], g_w1l[NL*DM*DFF];
__device__ __nv_bfloat16 g_w2h[NL*DFF*DM], g_w2l[NL*DFF*DM];
__device__ float g_x[SEQ*DM];
__device__ float g_t[SEQ*DM];
__device__ __nv_bfloat16 g_xh[SEQ*DM],  g_xl[SEQ*DM];
__device__ __nv_bfloat16 g_qkvh[(size_t)SEQ*3*DM], g_qkvl[(size_t)SEQ*3*DM];
__device__ __nv_bfloat16 g_cxh[SEQ*DM], g_cxl[SEQ*DM];
__device__ __nv_bfloat16 g_hh[SEQ*DFF], g_hl[SEQ*DFF];

// ---------------------------------------------------------------------------
// Helpers
// ---------------------------------------------------------------------------
__device__ __forceinline__ uint32_t smem_u32(const void* p) {
    return (uint32_t)__cvta_generic_to_shared(p);
}
__device__ __forceinline__ uint32_t packbf(float a, float b) {
    __nv_bfloat162 t = __floats2bfloat162_rn(a, b);
    return *reinterpret_cast<uint32_t*>(&t);
}
__device__ __forceinline__ float lores(float a) {
    return a - __bfloat162float(__float2bfloat16_rn(a));
}
__device__ __forceinline__ void cp16(uint32_t dst, const void* src) {
    asm volatile("cp.async.cg.shared.global [%0], [%1], 16;\n" :: "r"(dst), "l"(src));
}
__device__ __forceinline__ void cp_commit() {
    asm volatile("cp.async.commit_group;\n" ::);
}
template<int N>
__device__ __forceinline__ void cp_wait() {
    asm volatile("cp.async.wait_group %0;\n" :: "n"(N));
}
__device__ __forceinline__ void ldsm_x4(uint32_t* r, uint32_t addr) {
    asm volatile("ldmatrix.sync.aligned.m8n8.x4.shared.b16 {%0,%1,%2,%3}, [%4];\n"
                 : "=r"(r[0]), "=r"(r[1]), "=r"(r[2]), "=r"(r[3]) : "r"(addr));
}
__device__ __forceinline__ void ldsm_x4_t(uint32_t* r, uint32_t addr) {
    asm volatile("ldmatrix.sync.aligned.m8n8.x4.trans.shared.b16 {%0,%1,%2,%3}, [%4];\n"
                 : "=r"(r[0]), "=r"(r[1]), "=r"(r[2]), "=r"(r[3]) : "r"(addr));
}
__device__ __forceinline__ void mma_bf16(float* c, const uint32_t* a, const uint32_t* b) {
    asm volatile(
        "mma.sync.aligned.m16n8k16.row.col.f32.bf16.bf16.f32 "
        "{%0,%1,%2,%3}, {%4,%5,%6,%7}, {%8,%9}, {%0,%1,%2,%3};\n"
        : "+f"(c[0]), "+f"(c[1]), "+f"(c[2]), "+f"(c[3])
        : "r"(a[0]), "r"(a[1]), "r"(a[2]), "r"(a[3]), "r"(b[0]), "r"(b[1]));
}

// ---------------------------------------------------------------------------
// ONE fused prep kernel: x copy+split, QKV weight pack, QKV bias pack,
// Wo/W1/W2 splits.
// ---------------------------------------------------------------------------
#define N4_X    (SEQ*DM/4)
#define N4_QKV  ((size_t)NL*DM*3*DM/4)
#define N4_WO   (NL*DM*DM/4)
#define N4_W1   ((size_t)NL*DM*DFF/4)
#define N4_W2   N4_W1
#define N4_BQ   (NL*3*DM/4)
#define PREP_T  ((size_t)N4_X + N4_QKV + N4_WO + N4_W1 + N4_W2 + N4_BQ)

__global__ __launch_bounds__(256)
void prep_k(const float* __restrict__ x_in,
            const float* __restrict__ wq, const float* __restrict__ wk,
            const float* __restrict__ wv, const float* __restrict__ bq,
            const float* __restrict__ bk, const float* __restrict__ bv,
            const float* __restrict__ wo, const float* __restrict__ w1,
            const float* __restrict__ w2,
            float* __restrict__ xo, __nv_bfloat16* __restrict__ xh,
            __nv_bfloat16* __restrict__ xl,
            __nv_bfloat16* __restrict__ qkvH, __nv_bfloat16* __restrict__ qkvL,
            float* __restrict__ bqkv,
            __nv_bfloat16* __restrict__ woh, __nv_bfloat16* __restrict__ wol,
            __nv_bfloat16* __restrict__ w1h, __nv_bfloat16* __restrict__ w1l,
            __nv_bfloat16* __restrict__ w2h, __nv_bfloat16* __restrict__ w2l)
{
    size_t i = (size_t)blockIdx.x * 256 + threadIdx.x;
    if (i >= PREP_T) return;

    auto splitStore = [](float4 v, __nv_bfloat16* H, __nv_bfloat16* L, size_t i4) {
        ((uint32_t*)H)[i4*2]   = packbf(v.x, v.y);
        ((uint32_t*)H)[i4*2+1] = packbf(v.z, v.w);
        ((uint32_t*)L)[i4*2]   = packbf(lores(v.x), lores(v.y));
        ((uint32_t*)L)[i4*2+1] = packbf(lores(v.z), lores(v.w));
    };

    if (i < N4_X) {
        float4 v = ((const float4*)x_in)[i];
        ((float4*)xo)[i] = v;
        splitStore(v, xh, xl, i);
        return;
    }
    i -= N4_X;
    if (i < N4_QKV) {
        size_t e = i * 4;
        int j = (int)(e % (3 * DM));
        size_t rowl = e / (3 * DM);
        int s = j / DM, c = j % DM;
        const float* src = (s == 0) ? wq : ((s == 1) ? wk : wv);
        float4 v = *(const float4*)&src[rowl * DM + c];
        splitStore(v, qkvH, qkvL, i);
        return;
    }
    i -= N4_QKV;
    if (i < N4_WO) {
        splitStore(((const float4*)wo)[i], woh, wol, i);
        return;
    }
    i -= N4_WO;
    if (i < N4_W1) {
        splitStore(((const float4*)w1)[i], w1h, w1l, i);
        return;
    }
    i -= N4_W1;
    if (i < N4_W2) {
        splitStore(((const float4*)w2)[i], w2h, w2l, i);
        return;
    }
    i -= N4_W2;
    {
        size_t e = i * 4;
        int l = (int)(e / (3 * DM)), j = (int)(e % (3 * DM));
        int s = j / DM, c = j % DM;
        const float* src = (s == 0) ? bq : ((s == 1) ? bk : bv);
        ((float4*)bqkv)[i] = *(const float4*)&src[l * DM + c];
    }
}

// ---------------------------------------------------------------------------
// GEMM variant S: 256 threads, tile 128x128x32, warp tile 64x32, 4-stage.
// For N<=3072 GEMMs (QKV, Wo, W2).
// ---------------------------------------------------------------------------
#define GSM_STAGE 37888
#define GSM_TOTAL (4 * GSM_STAGE)

template<int ACT>
__global__ __launch_bounds__(256, 1)
void gemm_s(const __nv_bfloat16* __restrict__ Ahg, const __nv_bfloat16* __restrict__ Alg,
            const __nv_bfloat16* __restrict__ Bhg, const __nv_bfloat16* __restrict__ Blg,
            const float* __restrict__ bias,
            float* __restrict__ Cf, __nv_bfloat16* __restrict__ Ch,
            __nv_bfloat16* __restrict__ Cl, int N, int K)
{
    extern __shared__ char smem[];
    const int tid = threadIdx.x, lane = tid & 31, warp = tid >> 5;
    const int wm0 = (warp & 1) * 64, wn0 = (warp >> 1) * 32;
    const int bm0 = blockIdx.y * 128, bn0 = blockIdx.x * 128;

    auto Ah_s = [&](int s){ return (__nv_bfloat16*)(smem + s*GSM_STAGE); };
    auto Al_s = [&](int s){ return (__nv_bfloat16*)(smem + s*GSM_STAGE + 10240); };
    auto Bh_s = [&](int s){ return (__nv_bfloat16*)(smem + s*GSM_STAGE + 20480); };
    auto Bl_s = [&](int s){ return (__nv_bfloat16*)(smem + s*GSM_STAGE + 29184); };

    auto load_stage = [&](int s, int kt) {
        const int k0 = kt * 32;
        __nv_bfloat16 *ah = Ah_s(s), *al = Al_s(s), *bh = Bh_s(s), *bl = Bl_s(s);
#pragma unroll
        for (int p = 0; p < 2; p++) {
            int c = p * 256 + tid;
            int r = c >> 2, sg = c & 3;
            size_t go = (size_t)(bm0 + r) * K + k0 + sg * 8;
            cp16(smem_u32(ah + r*40 + sg*8), Ahg + go);
            cp16(smem_u32(al + r*40 + sg*8), Alg + go);
        }
#pragma unroll
        for (int p = 0; p < 2; p++) {
            int c = p * 256 + tid;
            int r = c >> 4, sg = c & 15;
            size_t go = (size_t)(k0 + r) * N + bn0 + sg * 8;
            cp16(smem_u32(bh + r*136 + sg*8), Bhg + go);
            cp16(smem_u32(bl + r*136 + sg*8), Blg + go);
        }
    };

    float acc[4][4][4];
#pragma unroll
    for (int i = 0; i < 4; i++)
#pragma unroll
        for (int j = 0; j < 4; j++)
#pragma unroll
            for (int q = 0; q < 4; q++) acc[i][j][q] = 0.f;

    const int KT = K / 32;
    load_stage(0, 0); cp_commit();
    load_stage(1, 1); cp_commit();
    load_stage(2, 2); cp_commit();

    for (int kt = 0; kt < KT; kt++) {
        cp_wait<2>();
        __syncthreads();

        if (kt + 3 < KT) load_stage((kt + 3) & 3, kt + 3);
        cp_commit();

        const int s = kt & 3;
        const __nv_bfloat16 *ah = Ah_s(s), *al = Al_s(s), *bh = Bh_s(s), *bl = Bl_s(s);
#pragma unroll
        for (int kc = 0; kc < 2; kc++) {
            const int kb = kc * 16;
            uint32_t aH[4][4], aL[4][4];
#pragma unroll
            for (int mt = 0; mt < 4; mt++) {
                int row = wm0 + mt * 16 + (lane & 15);
                int ko  = kb + ((lane >> 4) << 3);
                ldsm_x4(aH[mt], smem_u32(ah + row*40 + ko));
                ldsm_x4(aL[mt], smem_u32(al + row*40 + ko));
            }
            uint32_t bH[4][2], bL[4][2];
#pragma unroll
            for (int np = 0; np < 2; np++) {
                int g  = lane >> 3;
                int rk = kb + (lane & 7) + ((g & 1) << 3);
                int nc = wn0 + np * 16 + ((g >> 1) << 3);
                uint32_t t4[4];
                ldsm_x4_t(t4, smem_u32(bh + rk*136 + nc));
                bH[2*np][0] = t4[0]; bH[2*np][1] = t4[1];
                bH[2*np+1][0] = t4[2]; bH[2*np+1][1] = t4[3];
                ldsm_x4_t(t4, smem_u32(bl + rk*136 + nc));
                bL[2*np][0] = t4[0]; bL[2*np][1] = t4[1];
                bL[2*np+1][0] = t4[2]; bL[2*np+1][1] = t4[3];
            }
#pragma unroll
            for (int mt = 0; mt < 4; mt++)
#pragma unroll
                for (int nt = 0; nt < 4; nt++)
                    mma_bf16(acc[mt][nt], aH[mt], bH[nt]);
#pragma unroll
            for (int mt = 0; mt < 4; mt++)
#pragma unroll
                for (int nt = 0; nt < 4; nt++)
                    mma_bf16(acc[mt][nt], aL[mt], bH[nt]);
#pragma unroll
            for (int mt = 0; mt < 4; mt++)
#pragma unroll
                for (int nt = 0; nt < 4; nt++)
                    mma_bf16(acc[mt][nt], aH[mt], bL[nt]);
        }
    }

#pragma unroll
    for (int mt = 0; mt < 4; mt++) {
        int r0 = bm0 + wm0 + mt * 16 + (lane >> 2);
#pragma unroll
        for (int nt = 0; nt < 4; nt++) {
            int c = bn0 + wn0 + nt * 8 + (lane & 3) * 2;
            float b0 = bias[c], b1 = bias[c + 1];
            float v[4];
#pragma unroll
            for (int q = 0; q < 4; q++) {
                float x = acc[mt][nt][q] + ((q & 1) ? b1 : b0);
                if (ACT == 1) {
                    float tt = tanhf(0.7978845608028654f * (x + 0.044715f * x * x * x));
                    x = 0.5f * x * (1.f + tt);
                }
                v[q] = x;
            }
            size_t o0 = (size_t)r0 * N + c, o1 = (size_t)(r0 + 8) * N + c;
            if (Cf) {
                *(float2*)&Cf[o0] = make_float2(v[0], v[1]);
                *(float2*)&Cf[o1] = make_float2(v[2], v[3]);
            }
            if (Ch) {
                ((uint32_t*)Ch)[o0 >> 1] = packbf(v[0], v[1]);
                ((uint32_t*)Ch)[o1 >> 1] = packbf(v[2], v[3]);
                ((uint32_t*)Cl)[o0 >> 1] = packbf(lores(v[0]), lores(v[1]));
                ((uint32_t*)Cl)[o1 >> 1] = packbf(lores(v[2]), lores(v[3]));
            }
        }
    }
}

// ---------------------------------------------------------------------------
// GEMM variant T: 256 threads, tile 128x256x32, warp grid 2x4, warp tile
// 64x64, 3-stage cp.async. Halves smem read amplification vs gemm_s
// (A x4 + B x2 on a 2x-wide tile => ~0.17 B/MAC vs 0.26). For W1 (N=4096).
// smem per stage: Ah/Al 10240 each, Bh/Bl 16896 each (rows of 264 elems).
// ---------------------------------------------------------------------------
#define TSM_STAGE 54272
#define TSM_TOTAL (3 * TSM_STAGE)

template<int ACT>
__global__ __launch_bounds__(256, 1)
void gemm_t(const __nv_bfloat16* __restrict__ Ahg, const __nv_bfloat16* __restrict__ Alg,
            const __nv_bfloat16* __restrict__ Bhg, const __nv_bfloat16* __restrict__ Blg,
            const float* __restrict__ bias,
            float* __restrict__ Cf, __nv_bfloat16* __restrict__ Ch,
            __nv_bfloat16* __restrict__ Cl, int N, int K)
{
    extern __shared__ char smem[];
    const int tid = threadIdx.x, lane = tid & 31, warp = tid >> 5;
    const int wm0 = (warp & 1) * 64, wn0 = (warp >> 1) * 64;
    const int bm0 = blockIdx.y * 128, bn0 = blockIdx.x * 256;

    auto Ah_s = [&](int s){ return (__nv_bfloat16*)(smem + s*TSM_STAGE); };
    auto Al_s = [&](int s){ return (__nv_bfloat16*)(smem + s*TSM_STAGE + 10240); };
    auto Bh_s = [&](int s){ return (__nv_bfloat16*)(smem + s*TSM_STAGE + 20480); };
    auto Bl_s = [&](int s){ return (__nv_bfloat16*)(smem + s*TSM_STAGE + 37376); };

    auto load_stage = [&](int s, int kt) {
        const int k0 = kt * 32;
        __nv_bfloat16 *ah = Ah_s(s), *al = Al_s(s), *bh = Bh_s(s), *bl = Bl_s(s);
#pragma unroll
        for (int p = 0; p < 2; p++) {
            int c = p * 256 + tid;
            int r = c >> 2, sg = c & 3;
            size_t go = (size_t)(bm0 + r) * K + k0 + sg * 8;
            cp16(smem_u32(ah + r*40 + sg*8), Ahg + go);
            cp16(smem_u32(al + r*40 + sg*8), Alg + go);
        }
#pragma unroll
        for (int p = 0; p < 4; p++) {
            int c = p * 256 + tid;
            int r = c >> 5, sg = c & 31;
            size_t go = (size_t)(k0 + r) * N + bn0 + sg * 8;
            cp16(smem_u32(bh + r*264 + sg*8), Bhg + go);
            cp16(smem_u32(bl + r*264 + sg*8), Blg + go);
        }
    };

    float acc[4][8][4];
#pragma unroll
    for (int i = 0; i < 4; i++)
#pragma unroll
        for (int j = 0; j < 8; j++)
#pragma unroll
            for (int q = 0; q < 4; q++) acc[i][j][q] = 0.f;

    const int KT = K / 32;
    load_stage(0, 0); cp_commit();
    load_stage(1, 1); cp_commit();

    for (int kt = 0; kt < KT; kt++) {
        cp_wait<1>();
        __syncthreads();

        if (kt + 2 < KT) load_stage((kt + 2) % 3, kt + 2);
        cp_commit();

        const int s = kt % 3;
        const __nv_bfloat16 *ah = Ah_s(s), *al = Al_s(s), *bh = Bh_s(s), *bl = Bl_s(s);
#pragma unroll
        for (int kc = 0; kc < 2; kc++) {
            const int kb = kc * 16;
            uint32_t aH[4][4], aL[4][4];
#pragma unroll
            for (int mt = 0; mt < 4; mt++) {
                int row = wm0 + mt * 16 + (lane & 15);
                int ko  = kb + ((lane >> 4) << 3);
                ldsm_x4(aH[mt], smem_u32(ah + row*40 + ko));
                ldsm_x4(aL[mt], smem_u32(al + row*40 + ko));
            }
            // process N in two 32-col halves to bound register pressure
#pragma unroll
            for (int h = 0; h < 2; h++) {
                uint32_t bH[4][2], bL[4][2];
#pragma unroll
                for (int np = 0; np < 2; np++) {
                    int g  = lane >> 3;
                    int rk = kb + (lane & 7) + ((g & 1) << 3);
                    int nc = wn0 + h * 32 + np * 16 + ((g >> 1) << 3);
                    uint32_t t4[4];
                    ldsm_x4_t(t4, smem_u32(bh + rk*264 + nc));
                    bH[2*np][0] = t4[0]; bH[2*np][1] = t4[1];
                    bH[2*np+1][0] = t4[2]; bH[2*np+1][1] = t4[3];
                    ldsm_x4_t(t4, smem_u32(bl + rk*264 + nc));
                    bL[2*np][0] = t4[0]; bL[2*np][1] = t4[1];
                    bL[2*np+1][0] = t4[2]; bL[2*np+1][1] = t4[3];
                }
#pragma unroll
                for (int mt = 0; mt < 4; mt++)
#pragma unroll
                    for (int nt = 0; nt < 4; nt++)
                        mma_bf16(acc[mt][h*4+nt], aH[mt], bH[nt]);
#pragma unroll
                for (int mt = 0; mt < 4; mt++)
#pragma unroll
                    for (int nt = 0; nt < 4; nt++)
                        mma_bf16(acc[mt][h*4+nt], aL[mt], bH[nt]);
#pragma unroll
                for (int mt = 0; mt < 4; mt++)
#pragma unroll
                    for (int nt = 0; nt < 4; nt++)
                        mma_bf16(acc[mt][h*4+nt], aH[mt], bL[nt]);
            }
        }
    }

#pragma unroll
    for (int mt = 0; mt < 4; mt++) {
        int r0 = bm0 + wm0 + mt * 16 + (lane >> 2);
#pragma unroll
        for (int nt = 0; nt < 8; nt++) {
            int c = bn0 + wn0 + nt * 8 + (lane & 3) * 2;
            float b0 = bias[c], b1 = bias[c + 1];
            float v[4];
#pragma unroll
            for (int q = 0; q < 4; q++) {
                float x = acc[mt][nt][q] + ((q & 1) ? b1 : b0);
                if (ACT == 1) {
                    float tt = tanhf(0.7978845608028654f * (x + 0.044715f * x * x * x));
                    x = 0.5f * x * (1.f + tt);
                }
                v[q] = x;
            }
            size_t o0 = (size_t)r0 * N + c, o1 = (size_t)(r0 + 8) * N + c;
            if (Cf) {
                *(float2*)&Cf[o0] = make_float2(v[0], v[1]);
                *(float2*)&Cf[o1] = make_float2(v[2], v[3]);
            }
            if (Ch) {
                ((uint32_t*)Ch)[o0 >> 1] = packbf(v[0], v[1]);
                ((uint32_t*)Ch)[o1 >> 1] = packbf(v[2], v[3]);
                ((uint32_t*)Cl)[o0 >> 1] = packbf(lores(v[0]), lores(v[1]));
                ((uint32_t*)Cl)[o1 >> 1] = packbf(lores(v[2]), lores(v[3]));
            }
        }
    }
}

// ---------------------------------------------------------------------------
// Flash attention: per block = (q-block of 128 rows, head). Packed QKV input.
// ---------------------------------------------------------------------------
#define FSM_ARR   18432
#define FSM_KV0   (2 * FSM_ARR)
#define FSM_STAGE (4 * FSM_ARR)
#define FSM_TOTAL (FSM_KV0 + 2 * FSM_STAGE)

__global__ __launch_bounds__(256, 1)
void flash_k(const __nv_bfloat16* __restrict__ Qh, const __nv_bfloat16* __restrict__ Ql,
             const __nv_bfloat16* __restrict__ Kh, const __nv_bfloat16* __restrict__ Kl,
             const __nv_bfloat16* __restrict__ Vh, const __nv_bfloat16* __restrict__ Vl,
             __nv_bfloat16* __restrict__ Ch, __nv_bfloat16* __restrict__ Cl, int ldq)
{
    extern __shared__ char smem[];
    const int tid = threadIdx.x, lane = tid & 31, warp = tid >> 5;
    const int qb = blockIdx.x, head = blockIdx.y;
    const int col0 = head * DK;

    __nv_bfloat16* Qsh = (__nv_bfloat16*)smem;
    __nv_bfloat16* Qsl = (__nv_bfloat16*)(smem + FSM_ARR);
    auto Ksh = [&](int s){ return (__nv_bfloat16*)(smem + FSM_KV0 + s*FSM_STAGE); };
    auto Ksl = [&](int s){ return (__nv_bfloat16*)(smem + FSM_KV0 + s*FSM_STAGE + FSM_ARR); };
    auto Vsh = [&](int s){ return (__nv_bfloat16*)(smem + FSM_KV0 + s*FSM_STAGE + 2*FSM_ARR); };
    auto Vsl = [&](int s){ return (__nv_bfloat16*)(smem + FSM_KV0 + s*FSM_STAGE + 3*FSM_ARR); };

#pragma unroll
    for (int p = 0; p < 4; p++) {
        int c = p * 256 + tid;
        int r = c >> 3, sg = c & 7;
        size_t go = (size_t)(qb * 128 + r) * ldq + col0 + sg * 8;
        cp16(smem_u32(Qsh + r*72 + sg*8), Qh + go);
        cp16(smem_u32(Qsl + r*72 + sg*8), Ql + go);
    }
    auto load_kv = [&](int s, int t) {
#pragma unroll
        for (int p = 0; p < 4; p++) {
            int c = p * 256 + tid;
            int r = c >> 3, sg = c & 7;
            size_t go = (size_t)(t * 128 + r) * ldq + col0 + sg * 8;
            cp16(smem_u32(Ksh(s) + r*72 + sg*8), Kh + go);
            cp16(smem_u32(Ksl(s) + r*72 + sg*8), Kl + go);
            cp16(smem_u32(Vsh(s) + r*72 + sg*8), Vh + go);
            cp16(smem_u32(Vsl(s) + r*72 + sg*8), Vl + go);
        }
    };
    load_kv(0, 0);
    cp_commit();

    float oacc[8][4];
#pragma unroll
    for (int i = 0; i < 8; i++)
#pragma unroll
        for (int q = 0; q < 4; q++) oacc[i][q] = 0.f;
    float mrun[2] = {-INFINITY, -INFINITY};
    float lrun[2] = {0.f, 0.f};

    const int NT_KV = SEQ / 128;
    for (int t = 0; t < NT_KV; t++) {
        if (t + 1 < NT_KV) load_kv((t + 1) & 1, t + 1);
        cp_commit();
        cp_wait<1>();
        __syncthreads();

        const int s = t & 1;
        const __nv_bfloat16 *ksh = Ksh(s), *ksl = Ksl(s), *vsh = Vsh(s), *vsl = Vsl(s);

        float sacc[16][4];
#pragma unroll
        for (int i = 0; i < 16; i++)
#pragma unroll
            for (int q = 0; q < 4; q++) sacc[i][q] = 0.f;

#pragma unroll
        for (int kc = 0; kc < 4; kc++) {
            const int kb = kc * 16;
            uint32_t aH[4], aL[4];
            {
                int row = warp * 16 + (lane & 15);
                int ko  = kb + ((lane >> 4) << 3);
                ldsm_x4(aH, smem_u32(Qsh + row*72 + ko));
                ldsm_x4(aL, smem_u32(Qsl + row*72 + ko));
            }
#pragma unroll
            for (int np = 0; np < 8; np++) {
                int nrow = np * 16 + (lane & 7) + ((lane >> 4) << 3);
                int kbase = kb + (((lane >> 3) & 1) << 3);
                uint32_t bh4[4], bl4[4];
                ldsm_x4(bh4, smem_u32(ksh + nrow*72 + kbase));
                ldsm_x4(bl4, smem_u32(ksl + nrow*72 + kbase));
                mma_bf16(sacc[2*np],   aH, bh4);
                mma_bf16(sacc[2*np],   aL, bh4);
                mma_bf16(sacc[2*np],   aH, bl4);
                mma_bf16(sacc[2*np+1], aH, bh4 + 2);
                mma_bf16(sacc[2*np+1], aL, bh4 + 2);
                mma_bf16(sacc[2*np+1], aH, bl4 + 2);
            }
        }

        float mnew[2];
#pragma unroll
        for (int rr = 0; rr < 2; rr++) {
            float m = -INFINITY;
#pragma unroll
            for (int nt = 0; nt < 16; nt++) {
                sacc[nt][2*rr]   *= 0.125f;
                sacc[nt][2*rr+1] *= 0.125f;
                m = fmaxf(m, fmaxf(sacc[nt][2*rr], sacc[nt][2*rr+1]));
            }
            m = fmaxf(m, __shfl_xor_sync(0xffffffffu, m, 1));
            m = fmaxf(m, __shfl_xor_sync(0xffffffffu, m, 2));
            mnew[rr] = fmaxf(mrun[rr], m);
        }
        float sc0 = __expf(mrun[0] - mnew[0]);
        float sc1 = __expf(mrun[1] - mnew[1]);
        float ls0 = 0.f, ls1 = 0.f;
#pragma unroll
        for (int nt = 0; nt < 16; nt++) {
            float p0 = __expf(sacc[nt][0] - mnew[0]);
            float p1 = __expf(sacc[nt][1] - mnew[0]);
            float p2 = __expf(sacc[nt][2] - mnew[1]);
            float p3 = __expf(sacc[nt][3] - mnew[1]);
            sacc[nt][0] = p0; sacc[nt][1] = p1; sacc[nt][2] = p2; sacc[nt][3] = p3;
            ls0 += p0 + p1; ls1 += p2 + p3;
        }
        ls0 += __shfl_xor_sync(0xffffffffu, ls0, 1);
        ls0 += __shfl_xor_sync(0xffffffffu, ls0, 2);
        ls1 += __shfl_xor_sync(0xffffffffu, ls1, 1);
        ls1 += __shfl_xor_sync(0xffffffffu, ls1, 2);
        lrun[0] = lrun[0] * sc0 + ls0;
        lrun[1] = lrun[1] * sc1 + ls1;
        mrun[0] = mnew[0]; mrun[1] = mnew[1];
#pragma unroll
        for (int nt = 0; nt < 8; nt++) {
            oacc[nt][0] *= sc0; oacc[nt][1] *= sc0;
            oacc[nt][2] *= sc1; oacc[nt][3] *= sc1;
        }

#pragma unroll
        for (int kt = 0; kt < 8; kt++) {
            uint32_t pH[4], pL[4];
            pH[0] = packbf(sacc[2*kt][0],   sacc[2*kt][1]);
            pH[1] = packbf(sacc[2*kt][2],   sacc[2*kt][3]);
            pH[2] = packbf(sacc[2*kt+1][0], sacc[2*kt+1][1]);
            pH[3] = packbf(sacc[2*kt+1][2], sacc[2*kt+1][3]);
            pL[0] = packbf(lores(sacc[2*kt][0]),   lores(sacc[2*kt][1]));
            pL[1] = packbf(lores(sacc[2*kt][2]),   lores(sacc[2*kt][3]));
            pL[2] = packbf(lores(sacc[2*kt+1][0]), lores(sacc[2*kt+1][1]));
            pL[3] = packbf(lores(sacc[2*kt+1][2]), lores(sacc[2*kt+1][3]));
#pragma unroll
            for (int np = 0; np < 4; np++) {
                int g  = lane >> 3;
                int rk = kt * 16 + (lane & 7) + ((g & 1) << 3);
                int nc = np * 16 + ((g >> 1) << 3);
                uint32_t bh4[4], bl4[4];
                ldsm_x4_t(bh4, smem_u32(vsh + rk*72 + nc));
                ldsm_x4_t(bl4, smem_u32(vsl + rk*72 + nc));
                mma_bf16(oacc[2*np],   pH, bh4);
                mma_bf16(oacc[2*np],   pL, bh4);
                mma_bf16(oacc[2*np],   pH, bl4);
                mma_bf16(oacc[2*np+1], pH, bh4 + 2);
                mma_bf16(oacc[2*np+1], pL, bh4 + 2);
                mma_bf16(oacc[2*np+1], pH, bl4 + 2);
            }
        }
        __syncthreads();
    }

    float inv0 = 1.f / lrun[0], inv1 = 1.f / lrun[1];
    int r0 = qb * 128 + warp * 16 + (lane >> 2);
#pragma unroll
    for (int nt = 0; nt < 8; nt++) {
        int c = col0 + nt * 8 + (lane & 3) * 2;
        float v0 = oacc[nt][0] * inv0, v1 = oacc[nt][1] * inv0;
        float v2 = oacc[nt][2] * inv1, v3 = oacc[nt][3] * inv1;
        size_t o0 = (size_t)r0 * DM + c, o1 = (size_t)(r0 + 8) * DM + c;
        ((uint32_t*)Ch)[o0 >> 1] = packbf(v0, v1);
        ((uint32_t*)Ch)[o1 >> 1] = packbf(v2, v3);
        ((uint32_t*)Cl)[o0 >> 1] = packbf(lores(v0), lores(v1));
        ((uint32_t*)Cl)[o1 >> 1] = packbf(lores(v2), lores(v3));
    }
}

// ---------------------------------------------------------------------------
// Fused residual + LayerNorm (1024): out = LN(x+sub)*g + b, plus hi/lo split
// ---------------------------------------------------------------------------
__global__ __launch_bounds__(256)
void ln_k(const float* __restrict__ x, const float* __restrict__ sub,
          const float* __restrict__ g, const float* __restrict__ b,
          float* __restrict__ out, __nv_bfloat16* __restrict__ oh,
          __nv_bfloat16* __restrict__ ol)
{
    const int tid = threadIdx.x;
    const size_t base = (size_t)blockIdx.x * DM + tid * 4;

    float4 xv = *(const float4*)(x + base);
    float4 sv = *(const float4*)(sub + base);
    float v0 = xv.x + sv.x, v1 = xv.y + sv.y, v2 = xv.z + sv.z, v3 = xv.w + sv.w;

    __shared__ float red[256];
    red[tid] = v0 + v1 + v2 + v3; __syncthreads();
#pragma unroll
    for (int s = 128; s > 0; s >>= 1) {
        if (tid < s) red[tid] += red[tid + s];
        __syncthreads();
    }
    const float mu = red[0] * (1.f / DM);
    __syncthreads();

    const float d0 = v0 - mu, d1 = v1 - mu, d2 = v2 - mu, d3 = v3 - mu;
    red[tid] = d0*d0 + d1*d1 + d2*d2 + d3*d3; __syncthreads();
#pragma unroll
    for (int s = 128; s > 0; s >>= 1) {
        if (tid < s) red[tid] += red[tid + s];
        __syncthreads();
    }
    const float inv = rsqrtf(red[0] * (1.f / DM) + LN_EPS);

    float4 gv = *(const float4*)(g + tid * 4);
    float4 bv = *(const float4*)(b + tid * 4);
    float o0 = d0 * inv * gv.x + bv.x;
    float o1 = d1 * inv * gv.y + bv.y;
    float o2 = d2 * inv * gv.z + bv.z;
    float o3 = d3 * inv * gv.w + bv.w;
    *(float4*)(out + base) = make_float4(o0, o1, o2, o3);
    if (oh) {
        ((uint32_t*)oh)[base >> 1]       = packbf(o0, o1);
        ((uint32_t*)oh)[(base >> 1) + 1] = packbf(o2, o3);
        ((uint32_t*)ol)[base >> 1]       = packbf(lores(o0), lores(o1));
        ((uint32_t*)ol)[(base >> 1) + 1] = packbf(lores(o2), lores(o3));
    }
}

// ---------------------------------------------------------------------------
// Host launcher
// ---------------------------------------------------------------------------
extern "C" void kernel_launch(void* const* d_in, const int* in_sizes, int n_in,
                              void* d_out, int out_size)
{
    (void)in_sizes; (void)n_in; (void)out_size;

    const float* x_in = (const float*)d_in[0];
    const float* wq  = (const float*)d_in[1];
    const float* bq  = (const float*)d_in[2];
    const float* wk  = (const float*)d_in[3];
    const float* bk  = (const float*)d_in[4];
    const float* wv  = (const float*)d_in[5];
    const float* bv  = (const float*)d_in[6];
    const float* wo  = (const float*)d_in[7];
    const float* bo  = (const float*)d_in[8];
    const float* w1  = (const float*)d_in[9];
    const float* b1  = (const float*)d_in[10];
    const float* w2  = (const float*)d_in[11];
    const float* b2  = (const float*)d_in[12];
    const float* ln1g = (const float*)d_in[13];
    const float* ln1b = (const float*)d_in[14];
    const float* ln2g = (const float*)d_in[15];
    const float* ln2b = (const float*)d_in[16];

    static bool attr_done = false;
    if (!attr_done) {
        cudaFuncSetAttribute(gemm_s<0>, cudaFuncAttributeMaxDynamicSharedMemorySize, GSM_TOTAL);
        cudaFuncSetAttribute(gemm_s<1>, cudaFuncAttributeMaxDynamicSharedMemorySize, GSM_TOTAL);
        cudaFuncSetAttribute(gemm_t<1>, cudaFuncAttributeMaxDynamicSharedMemorySize, TSM_TOTAL);
        cudaFuncSetAttribute(flash_k,   cudaFuncAttributeMaxDynamicSharedMemorySize, FSM_TOTAL);
        attr_done = true;
    }

    float *x, *t, *bqkv;
    __nv_bfloat16 *wqkvh,*wqkvl,*woh,*wol,*w1h,*w1l,*w2h,*w2l;
    __nv_bfloat16 *xh,*xl,*qkvh,*qkvl,*cxh,*cxl,*hh,*hl;
    cudaGetSymbolAddress((void**)&x, g_x);
    cudaGetSymbolAddress((void**)&t, g_t);
    cudaGetSymbolAddress((void**)&bqkv, g_bqkv);
    cudaGetSymbolAddress((void**)&wqkvh, g_wqkvh); cudaGetSymbolAddress((void**)&wqkvl, g_wqkvl);
    cudaGetSymbolAddress((void**)&woh, g_woh);     cudaGetSymbolAddress((void**)&wol, g_wol);
    cudaGetSymbolAddress((void**)&w1h, g_w1h);     cudaGetSymbolAddress((void**)&w1l, g_w1l);
    cudaGetSymbolAddress((void**)&w2h, g_w2h);     cudaGetSymbolAddress((void**)&w2l, g_w2l);
    cudaGetSymbolAddress((void**)&xh, g_xh);       cudaGetSymbolAddress((void**)&xl, g_xl);
    cudaGetSymbolAddress((void**)&qkvh, g_qkvh);   cudaGetSymbolAddress((void**)&qkvl, g_qkvl);
    cudaGetSymbolAddress((void**)&cxh, g_cxh);     cudaGetSymbolAddress((void**)&cxl, g_cxl);
    cudaGetSymbolAddress((void**)&hh, g_hh);       cudaGetSymbolAddress((void**)&hl, g_hl);

    // ONE fused prep launch
    prep_k<<<(int)((PREP_T + 255) / 256), 256>>>(
        x_in, wq, wk, wv, bq, bk, bv, wo, w1, w2,
        x, xh, xl, wqkvh, wqkvl, bqkv, woh, wol, w1h, w1l, w2h, w2l);

    dim3 gQKV(3*DM / 128, SEQ / 128);   // 24 x 16 = 384 CTAs
    dim3 gP(DM / 128, SEQ / 128);       // 8 x 16 = 128 CTAs
    dim3 gF1(DFF / 256, SEQ / 128);     // 16 x 16 = 256 CTAs (gemm_t tiles)
    dim3 gAtt(SEQ / 128, NH);

    for (int l = 0; l < NL; l++) {
        const __nv_bfloat16 *Wqkvh = wqkvh + (size_t)l*DM*3*DM, *Wqkvl = wqkvl + (size_t)l*DM*3*DM;
        const __nv_bfloat16 *Woh = woh + (size_t)l*DM*DM,  *Wol = wol + (size_t)l*DM*DM;
        const __nv_bfloat16 *W1h = w1h + (size_t)l*DM*DFF, *W1l = w1l + (size_t)l*DM*DFF;
        const __nv_bfloat16 *W2h = w2h + (size_t)l*DFF*DM, *W2l = w2l + (size_t)l*DFF*DM;
        const float *Bqkv = bqkv + (size_t)l*3*DM;
        const float *Bo = bo + (size_t)l*DM;
        const float *B1 = b1 + (size_t)l*DFF, *B2 = b2 + (size_t)l*DM;
        const float *G1 = ln1g + (size_t)l*DM, *Be1 = ln1b + (size_t)l*DM;
        const float *G2 = ln2g + (size_t)l*DM, *Be2 = ln2b + (size_t)l*DM;

        // fused QKV projection: [SEQ,1024] @ [1024,3072] -> qkv hi/lo
        gemm_s<0><<<gQKV,256,GSM_TOTAL>>>(xh, xl, Wqkvh, Wqkvl, Bqkv,
                                          nullptr, qkvh, qkvl, 3*DM, DM);
        // fused attention (Q at col 0, K at col DM, V at col 2*DM of qkv)
        flash_k<<<gAtt,256,FSM_TOTAL>>>(qkvh, qkvl, qkvh + DM, qkvl + DM,
                                        qkvh + 2*DM, qkvl + 2*DM, cxh, cxl, 3*DM);
        // attn_out = ctx @ Wo + bo (fp32)
        gemm_s<0><<<gP,256,GSM_TOTAL>>>(cxh, cxl, Woh, Wol, Bo, t, nullptr, nullptr, DM, DM);
        // x = LN1(x + attn_out), also split
        ln_k<<<SEQ,256>>>(x, t, G1, Be1, x, xh, xl);
        // h = gelu(x @ W1 + b1) -> hi/lo : wide-tile kernel (128x256, warp 64x64)
        gemm_t<1><<<gF1,256,TSM_TOTAL>>>(xh, xl, W1h, W1l, B1, nullptr, hh, hl, DFF, DM);
        // ffn_out = h @ W2 + b2 (fp32)
        gemm_s<0><<<gP,256,GSM_TOTAL>>>(hh, hl, W2h, W2l, B2, t, nullptr, nullptr, DM, DFF);
        // x = LN2(x + ffn_out); final layer -> d_out
        float* outp = (l == NL - 1) ? (float*)d_out : x;
        __nv_bfloat16* oh = (l == NL - 1) ? nullptr : xh;
        __nv_bfloat16* ol = (l == NL - 1) ? nullptr : xl;
        ln_k<<<SEQ,256>>>(x, t, G2, Be2, outp, oh, ol);
    }
}

// round 14
// speedup vs baseline: 1.0078x; 1.0078x over previous
#include <cuda_runtime.h>
#include <cuda_bf16.h>
#include <math.h>
#include <stdint.h>

// Problem constants
#define SEQ   2048
#define DM    1024
#define NH    16
#define DK    64
#define DFF   4096
#define NL    4
#define LN_EPS 1e-5f

// ---------------------------------------------------------------------------
// Scratch (static device globals: allocation-free kernel_launch)
// ---------------------------------------------------------------------------
__device__ __nv_bfloat16 g_wqkvh[(size_t)NL*DM*3*DM], g_wqkvl[(size_t)NL*DM*3*DM];
__device__ float         g_bqkv[NL*3*DM];
__device__ __nv_bfloat16 g_woh[NL*DM*DM],  g_wol[NL*DM*DM];
__device__ __nv_bfloat16 g_w1h[NL*DM*DFF], g_w1l[NL*DM*DFF];
__device__ __nv_bfloat16 g_w2h[NL*DFF*DM], g_w2l[NL*DFF*DM];
__device__ float g_x[SEQ*DM];
__device__ float g_t[SEQ*DM];
__device__ __nv_bfloat16 g_xh[SEQ*DM],  g_xl[SEQ*DM];
__device__ __nv_bfloat16 g_qkvh[(size_t)SEQ*3*DM], g_qkvl[(size_t)SEQ*3*DM];
__device__ __nv_bfloat16 g_cxh[SEQ*DM], g_cxl[SEQ*DM];
__device__ __nv_bfloat16 g_hh[SEQ*DFF], g_hl[SEQ*DFF];

// ---------------------------------------------------------------------------
// Helpers
// ---------------------------------------------------------------------------
__device__ __forceinline__ uint32_t smem_u32(const void* p) {
    return (uint32_t)__cvta_generic_to_shared(p);
}
__device__ __forceinline__ uint32_t packbf(float a, float b) {
    __nv_bfloat162 t = __floats2bfloat162_rn(a, b);
    return *reinterpret_cast<uint32_t*>(&t);
}
__device__ __forceinline__ float lores(float a) {
    return a - __bfloat162float(__float2bfloat16_rn(a));
}
__device__ __forceinline__ void cp16(uint32_t dst, const void* src) {
    asm volatile("cp.async.cg.shared.global [%0], [%1], 16;\n" :: "r"(dst), "l"(src));
}
__device__ __forceinline__ void cp_commit() {
    asm volatile("cp.async.commit_group;\n" ::);
}
template<int N>
__device__ __forceinline__ void cp_wait() {
    asm volatile("cp.async.wait_group %0;\n" :: "n"(N));
}
__device__ __forceinline__ void ldsm_x4(uint32_t* r, uint32_t addr) {
    asm volatile("ldmatrix.sync.aligned.m8n8.x4.shared.b16 {%0,%1,%2,%3}, [%4];\n"
                 : "=r"(r[0]), "=r"(r[1]), "=r"(r[2]), "=r"(r[3]) : "r"(addr));
}
__device__ __forceinline__ void ldsm_x4_t(uint32_t* r, uint32_t addr) {
    asm volatile("ldmatrix.sync.aligned.m8n8.x4.trans.shared.b16 {%0,%1,%2,%3}, [%4];\n"
                 : "=r"(r[0]), "=r"(r[1]), "=r"(r[2]), "=r"(r[3]) : "r"(addr));
}
__device__ __forceinline__ void mma_bf16(float* c, const uint32_t* a, const uint32_t* b) {
    asm volatile(
        "mma.sync.aligned.m16n8k16.row.col.f32.bf16.bf16.f32 "
        "{%0,%1,%2,%3}, {%4,%5,%6,%7}, {%8,%9}, {%0,%1,%2,%3};\n"
        : "+f"(c[0]), "+f"(c[1]), "+f"(c[2]), "+f"(c[3])
        : "r"(a[0]), "r"(a[1]), "r"(a[2]), "r"(a[3]), "r"(b[0]), "r"(b[1]));
}

// ---------------------------------------------------------------------------
// ONE fused prep kernel: x copy+split, QKV weight pack, QKV bias pack,
// Wo/W1/W2 splits.
// ---------------------------------------------------------------------------
#define N4_X    (SEQ*DM/4)
#define N4_QKV  ((size_t)NL*DM*3*DM/4)
#define N4_WO   (NL*DM*DM/4)
#define N4_W1   ((size_t)NL*DM*DFF/4)
#define N4_W2   N4_W1
#define N4_BQ   (NL*3*DM/4)
#define PREP_T  ((size_t)N4_X + N4_QKV + N4_WO + N4_W1 + N4_W2 + N4_BQ)

__global__ __launch_bounds__(256)
void prep_k(const float* __restrict__ x_in,
            const float* __restrict__ wq, const float* __restrict__ wk,
            const float* __restrict__ wv, const float* __restrict__ bq,
            const float* __restrict__ bk, const float* __restrict__ bv,
            const float* __restrict__ wo, const float* __restrict__ w1,
            const float* __restrict__ w2,
            float* __restrict__ xo, __nv_bfloat16* __restrict__ xh,
            __nv_bfloat16* __restrict__ xl,
            __nv_bfloat16* __restrict__ qkvH, __nv_bfloat16* __restrict__ qkvL,
            float* __restrict__ bqkv,
            __nv_bfloat16* __restrict__ woh, __nv_bfloat16* __restrict__ wol,
            __nv_bfloat16* __restrict__ w1h, __nv_bfloat16* __restrict__ w1l,
            __nv_bfloat16* __restrict__ w2h, __nv_bfloat16* __restrict__ w2l)
{
    size_t i = (size_t)blockIdx.x * 256 + threadIdx.x;
    if (i >= PREP_T) return;

    auto splitStore = [](float4 v, __nv_bfloat16* H, __nv_bfloat16* L, size_t i4) {
        ((uint32_t*)H)[i4*2]   = packbf(v.x, v.y);
        ((uint32_t*)H)[i4*2+1] = packbf(v.z, v.w);
        ((uint32_t*)L)[i4*2]   = packbf(lores(v.x), lores(v.y));
        ((uint32_t*)L)[i4*2+1] = packbf(lores(v.z), lores(v.w));
    };

    if (i < N4_X) {
        float4 v = ((const float4*)x_in)[i];
        ((float4*)xo)[i] = v;
        splitStore(v, xh, xl, i);
        return;
    }
    i -= N4_X;
    if (i < N4_QKV) {
        size_t e = i * 4;
        int j = (int)(e % (3 * DM));
        size_t rowl = e / (3 * DM);
        int s = j / DM, c = j % DM;
        const float* src = (s == 0) ? wq : ((s == 1) ? wk : wv);
        float4 v = *(const float4*)&src[rowl * DM + c];
        splitStore(v, qkvH, qkvL, i);
        return;
    }
    i -= N4_QKV;
    if (i < N4_WO) {
        splitStore(((const float4*)wo)[i], woh, wol, i);
        return;
    }
    i -= N4_WO;
    if (i < N4_W1) {
        splitStore(((const float4*)w1)[i], w1h, w1l, i);
        return;
    }
    i -= N4_W1;
    if (i < N4_W2) {
        splitStore(((const float4*)w2)[i], w2h, w2l, i);
        return;
    }
    i -= N4_W2;
    {
        size_t e = i * 4;
        int l = (int)(e / (3 * DM)), j = (int)(e % (3 * DM));
        int s = j / DM, c = j % DM;
        const float* src = (s == 0) ? bq : ((s == 1) ? bk : bv);
        ((float4*)bqkv)[i] = *(const float4*)&src[l * DM + c];
    }
}

// ---------------------------------------------------------------------------
// GEMM variant H: 128 threads (4 warps, 2x2), tile 128x64x32, warp tile 64x32,
// 3-stage cp.async, __launch_bounds__(128, 2) -> TWO independent CTAs per SM
// (RF: 2*128*246 ~ 63K regs; smem: 2*89KB ~ 178KB). Decoupled barriers are the
// point: while one CTA waits, the other's warps feed the tensor pipe.
// smem strides: A rows 40 elems (80B), B rows 72 elems (144B).
// Stage layout: Ah @0 (10240), Al @10240, Bh @20480 (4608), Bl @25088 (4608).
// ---------------------------------------------------------------------------
#define HSM_STAGE 29696
#define HSM_TOTAL (3 * HSM_STAGE)

template<int ACT>
__global__ __launch_bounds__(128, 2)
void gemm_h(const __nv_bfloat16* __restrict__ Ahg, const __nv_bfloat16* __restrict__ Alg,
            const __nv_bfloat16* __restrict__ Bhg, const __nv_bfloat16* __restrict__ Blg,
            const float* __restrict__ bias,
            float* __restrict__ Cf, __nv_bfloat16* __restrict__ Ch,
            __nv_bfloat16* __restrict__ Cl, int N, int K)
{
    extern __shared__ char smem[];
    const int tid = threadIdx.x, lane = tid & 31, warp = tid >> 5;
    const int wm0 = (warp & 1) * 64, wn0 = (warp >> 1) * 32;
    const int bm0 = blockIdx.y * 128, bn0 = blockIdx.x * 64;

    auto Ah_s = [&](int s){ return (__nv_bfloat16*)(smem + s*HSM_STAGE); };
    auto Al_s = [&](int s){ return (__nv_bfloat16*)(smem + s*HSM_STAGE + 10240); };
    auto Bh_s = [&](int s){ return (__nv_bfloat16*)(smem + s*HSM_STAGE + 20480); };
    auto Bl_s = [&](int s){ return (__nv_bfloat16*)(smem + s*HSM_STAGE + 25088); };

    auto load_stage = [&](int s, int kt) {
        const int k0 = kt * 32;
        __nv_bfloat16 *ah = Ah_s(s), *al = Al_s(s), *bh = Bh_s(s), *bl = Bl_s(s);
#pragma unroll
        for (int p = 0; p < 4; p++) {
            int c = p * 128 + tid;
            int r = c >> 2, sg = c & 3;        // 128 rows x 4 8-elem chunks
            size_t go = (size_t)(bm0 + r) * K + k0 + sg * 8;
            cp16(smem_u32(ah + r*40 + sg*8), Ahg + go);
            cp16(smem_u32(al + r*40 + sg*8), Alg + go);
        }
#pragma unroll
        for (int p = 0; p < 2; p++) {
            int c = p * 128 + tid;
            int r = c >> 3, sg = c & 7;        // 32 rows x 8 8-elem chunks
            size_t go = (size_t)(k0 + r) * N + bn0 + sg * 8;
            cp16(smem_u32(bh + r*72 + sg*8), Bhg + go);
            cp16(smem_u32(bl + r*72 + sg*8), Blg + go);
        }
    };

    float acc[4][4][4];
#pragma unroll
    for (int i = 0; i < 4; i++)
#pragma unroll
        for (int j = 0; j < 4; j++)
#pragma unroll
            for (int q = 0; q < 4; q++) acc[i][j][q] = 0.f;

    const int KT = K / 32;
    load_stage(0, 0); cp_commit();
    load_stage(1, 1); cp_commit();

    for (int kt = 0; kt < KT; kt++) {
        cp_wait<1>();
        __syncthreads();   // stage kt arrived; all warps done with compute kt-1

        if (kt + 2 < KT) load_stage((kt + 2) % 3, kt + 2);
        cp_commit();

        const int s = kt % 3;
        const __nv_bfloat16 *ah = Ah_s(s), *al = Al_s(s), *bh = Bh_s(s), *bl = Bl_s(s);
#pragma unroll
        for (int kc = 0; kc < 2; kc++) {
            const int kb = kc * 16;
            uint32_t aH[4][4], aL[4][4];
#pragma unroll
            for (int mt = 0; mt < 4; mt++) {
                int row = wm0 + mt * 16 + (lane & 15);
                int ko  = kb + ((lane >> 4) << 3);
                ldsm_x4(aH[mt], smem_u32(ah + row*40 + ko));
                ldsm_x4(aL[mt], smem_u32(al + row*40 + ko));
            }
            uint32_t bH[4][2], bL[4][2];
#pragma unroll
            for (int np = 0; np < 2; np++) {
                int g  = lane >> 3;
                int rk = kb + (lane & 7) + ((g & 1) << 3);
                int nc = wn0 + np * 16 + ((g >> 1) << 3);
                uint32_t t4[4];
                ldsm_x4_t(t4, smem_u32(bh + rk*72 + nc));
                bH[2*np][0] = t4[0]; bH[2*np][1] = t4[1];
                bH[2*np+1][0] = t4[2]; bH[2*np+1][1] = t4[3];
                ldsm_x4_t(t4, smem_u32(bl + rk*72 + nc));
                bL[2*np][0] = t4[0]; bL[2*np][1] = t4[1];
                bL[2*np+1][0] = t4[2]; bL[2*np+1][1] = t4[3];
            }
#pragma unroll
            for (int mt = 0; mt < 4; mt++)
#pragma unroll
                for (int nt = 0; nt < 4; nt++)
                    mma_bf16(acc[mt][nt], aH[mt], bH[nt]);
#pragma unroll
            for (int mt = 0; mt < 4; mt++)
#pragma unroll
                for (int nt = 0; nt < 4; nt++)
                    mma_bf16(acc[mt][nt], aL[mt], bH[nt]);
#pragma unroll
            for (int mt = 0; mt < 4; mt++)
#pragma unroll
                for (int nt = 0; nt < 4; nt++)
                    mma_bf16(acc[mt][nt], aH[mt], bL[nt]);
        }
    }

#pragma unroll
    for (int mt = 0; mt < 4; mt++) {
        int r0 = bm0 + wm0 + mt * 16 + (lane >> 2);
#pragma unroll
        for (int nt = 0; nt < 4; nt++) {
            int c = bn0 + wn0 + nt * 8 + (lane & 3) * 2;
            float b0 = bias[c], b1 = bias[c + 1];
            float v[4];
#pragma unroll
            for (int q = 0; q < 4; q++) {
                float x = acc[mt][nt][q] + ((q & 1) ? b1 : b0);
                if (ACT == 1) {
                    float tt = tanhf(0.7978845608028654f * (x + 0.044715f * x * x * x));
                    x = 0.5f * x * (1.f + tt);
                }
                v[q] = x;
            }
            size_t o0 = (size_t)r0 * N + c, o1 = (size_t)(r0 + 8) * N + c;
            if (Cf) {
                *(float2*)&Cf[o0] = make_float2(v[0], v[1]);
                *(float2*)&Cf[o1] = make_float2(v[2], v[3]);
            }
            if (Ch) {
                ((uint32_t*)Ch)[o0 >> 1] = packbf(v[0], v[1]);
                ((uint32_t*)Ch)[o1 >> 1] = packbf(v[2], v[3]);
                ((uint32_t*)Cl)[o0 >> 1] = packbf(lores(v[0]), lores(v[1]));
                ((uint32_t*)Cl)[o1 >> 1] = packbf(lores(v[2]), lores(v[3]));
            }
        }
    }
}

// ---------------------------------------------------------------------------
// Flash attention: per block = (q-block of 128 rows, head). Packed QKV input.
// ---------------------------------------------------------------------------
#define FSM_ARR   18432
#define FSM_KV0   (2 * FSM_ARR)
#define FSM_STAGE (4 * FSM_ARR)
#define FSM_TOTAL (FSM_KV0 + 2 * FSM_STAGE)

__global__ __launch_bounds__(256, 1)
void flash_k(const __nv_bfloat16* __restrict__ Qh, const __nv_bfloat16* __restrict__ Ql,
             const __nv_bfloat16* __restrict__ Kh, const __nv_bfloat16* __restrict__ Kl,
             const __nv_bfloat16* __restrict__ Vh, const __nv_bfloat16* __restrict__ Vl,
             __nv_bfloat16* __restrict__ Ch, __nv_bfloat16* __restrict__ Cl, int ldq)
{
    extern __shared__ char smem[];
    const int tid = threadIdx.x, lane = tid & 31, warp = tid >> 5;
    const int qb = blockIdx.x, head = blockIdx.y;
    const int col0 = head * DK;

    __nv_bfloat16* Qsh = (__nv_bfloat16*)smem;
    __nv_bfloat16* Qsl = (__nv_bfloat16*)(smem + FSM_ARR);
    auto Ksh = [&](int s){ return (__nv_bfloat16*)(smem + FSM_KV0 + s*FSM_STAGE); };
    auto Ksl = [&](int s){ return (__nv_bfloat16*)(smem + FSM_KV0 + s*FSM_STAGE + FSM_ARR); };
    auto Vsh = [&](int s){ return (__nv_bfloat16*)(smem + FSM_KV0 + s*FSM_STAGE + 2*FSM_ARR); };
    auto Vsl = [&](int s){ return (__nv_bfloat16*)(smem + FSM_KV0 + s*FSM_STAGE + 3*FSM_ARR); };

#pragma unroll
    for (int p = 0; p < 4; p++) {
        int c = p * 256 + tid;
        int r = c >> 3, sg = c & 7;
        size_t go = (size_t)(qb * 128 + r) * ldq + col0 + sg * 8;
        cp16(smem_u32(Qsh + r*72 + sg*8), Qh + go);
        cp16(smem_u32(Qsl + r*72 + sg*8), Ql + go);
    }
    auto load_kv = [&](int s, int t) {
#pragma unroll
        for (int p = 0; p < 4; p++) {
            int c = p * 256 + tid;
            int r = c >> 3, sg = c & 7;
            size_t go = (size_t)(t * 128 + r) * ldq + col0 + sg * 8;
            cp16(smem_u32(Ksh(s) + r*72 + sg*8), Kh + go);
            cp16(smem_u32(Ksl(s) + r*72 + sg*8), Kl + go);
            cp16(smem_u32(Vsh(s) + r*72 + sg*8), Vh + go);
            cp16(smem_u32(Vsl(s) + r*72 + sg*8), Vl + go);
        }
    };
    load_kv(0, 0);
    cp_commit();

    float oacc[8][4];
#pragma unroll
    for (int i = 0; i < 8; i++)
#pragma unroll
        for (int q = 0; q < 4; q++) oacc[i][q] = 0.f;
    float mrun[2] = {-INFINITY, -INFINITY};
    float lrun[2] = {0.f, 0.f};

    const int NT_KV = SEQ / 128;
    for (int t = 0; t < NT_KV; t++) {
        if (t + 1 < NT_KV) load_kv((t + 1) & 1, t + 1);
        cp_commit();
        cp_wait<1>();
        __syncthreads();

        const int s = t & 1;
        const __nv_bfloat16 *ksh = Ksh(s), *ksl = Ksl(s), *vsh = Vsh(s), *vsl = Vsl(s);

        float sacc[16][4];
#pragma unroll
        for (int i = 0; i < 16; i++)
#pragma unroll
            for (int q = 0; q < 4; q++) sacc[i][q] = 0.f;

#pragma unroll
        for (int kc = 0; kc < 4; kc++) {
            const int kb = kc * 16;
            uint32_t aH[4], aL[4];
            {
                int row = warp * 16 + (lane & 15);
                int ko  = kb + ((lane >> 4) << 3);
                ldsm_x4(aH, smem_u32(Qsh + row*72 + ko));
                ldsm_x4(aL, smem_u32(Qsl + row*72 + ko));
            }
#pragma unroll
            for (int np = 0; np < 8; np++) {
                int nrow = np * 16 + (lane & 7) + ((lane >> 4) << 3);
                int kbase = kb + (((lane >> 3) & 1) << 3);
                uint32_t bh4[4], bl4[4];
                ldsm_x4(bh4, smem_u32(ksh + nrow*72 + kbase));
                ldsm_x4(bl4, smem_u32(ksl + nrow*72 + kbase));
                mma_bf16(sacc[2*np],   aH, bh4);
                mma_bf16(sacc[2*np],   aL, bh4);
                mma_bf16(sacc[2*np],   aH, bl4);
                mma_bf16(sacc[2*np+1], aH, bh4 + 2);
                mma_bf16(sacc[2*np+1], aL, bh4 + 2);
                mma_bf16(sacc[2*np+1], aH, bl4 + 2);
            }
        }

        float mnew[2];
#pragma unroll
        for (int rr = 0; rr < 2; rr++) {
            float m = -INFINITY;
#pragma unroll
            for (int nt = 0; nt < 16; nt++) {
                sacc[nt][2*rr]   *= 0.125f;
                sacc[nt][2*rr+1] *= 0.125f;
                m = fmaxf(m, fmaxf(sacc[nt][2*rr], sacc[nt][2*rr+1]));
            }
            m = fmaxf(m, __shfl_xor_sync(0xffffffffu, m, 1));
            m = fmaxf(m, __shfl_xor_sync(0xffffffffu, m, 2));
            mnew[rr] = fmaxf(mrun[rr], m);
        }
        float sc0 = __expf(mrun[0] - mnew[0]);
        float sc1 = __expf(mrun[1] - mnew[1]);
        float ls0 = 0.f, ls1 = 0.f;
#pragma unroll
        for (int nt = 0; nt < 16; nt++) {
            float p0 = __expf(sacc[nt][0] - mnew[0]);
            float p1 = __expf(sacc[nt][1] - mnew[0]);
            float p2 = __expf(sacc[nt][2] - mnew[1]);
            float p3 = __expf(sacc[nt][3] - mnew[1]);
            sacc[nt][0] = p0; sacc[nt][1] = p1; sacc[nt][2] = p2; sacc[nt][3] = p3;
            ls0 += p0 + p1; ls1 += p2 + p3;
        }
        ls0 += __shfl_xor_sync(0xffffffffu, ls0, 1);
        ls0 += __shfl_xor_sync(0xffffffffu, ls0, 2);
        ls1 += __shfl_xor_sync(0xffffffffu, ls1, 1);
        ls1 += __shfl_xor_sync(0xffffffffu, ls1, 2);
        lrun[0] = lrun[0] * sc0 + ls0;
        lrun[1] = lrun[1] * sc1 + ls1;
        mrun[0] = mnew[0]; mrun[1] = mnew[1];
#pragma unroll
        for (int nt = 0; nt < 8; nt++) {
            oacc[nt][0] *= sc0; oacc[nt][1] *= sc0;
            oacc[nt][2] *= sc1; oacc[nt][3] *= sc1;
        }

#pragma unroll
        for (int kt = 0; kt < 8; kt++) {
            uint32_t pH[4], pL[4];
            pH[0] = packbf(sacc[2*kt][0],   sacc[2*kt][1]);
            pH[1] = packbf(sacc[2*kt][2],   sacc[2*kt][3]);
            pH[2] = packbf(sacc[2*kt+1][0], sacc[2*kt+1][1]);
            pH[3] = packbf(sacc[2*kt+1][2], sacc[2*kt+1][3]);
            pL[0] = packbf(lores(sacc[2*kt][0]),   lores(sacc[2*kt][1]));
            pL[1] = packbf(lores(sacc[2*kt][2]),   lores(sacc[2*kt][3]));
            pL[2] = packbf(lores(sacc[2*kt+1][0]), lores(sacc[2*kt+1][1]));
            pL[3] = packbf(lores(sacc[2*kt+1][2]), lores(sacc[2*kt+1][3]));
#pragma unroll
            for (int np = 0; np < 4; np++) {
                int g  = lane >> 3;
                int rk = kt * 16 + (lane & 7) + ((g & 1) << 3);
                int nc = np * 16 + ((g >> 1) << 3);
                uint32_t bh4[4], bl4[4];
                ldsm_x4_t(bh4, smem_u32(vsh + rk*72 + nc));
                ldsm_x4_t(bl4, smem_u32(vsl + rk*72 + nc));
                mma_bf16(oacc[2*np],   pH, bh4);
                mma_bf16(oacc[2*np],   pL, bh4);
                mma_bf16(oacc[2*np],   pH, bl4);
                mma_bf16(oacc[2*np+1], pH, bh4 + 2);
                mma_bf16(oacc[2*np+1], pL, bh4 + 2);
                mma_bf16(oacc[2*np+1], pH, bl4 + 2);
            }
        }
        __syncthreads();
    }

    float inv0 = 1.f / lrun[0], inv1 = 1.f / lrun[1];
    int r0 = qb * 128 + warp * 16 + (lane >> 2);
#pragma unroll
    for (int nt = 0; nt < 8; nt++) {
        int c = col0 + nt * 8 + (lane & 3) * 2;
        float v0 = oacc[nt][0] * inv0, v1 = oacc[nt][1] * inv0;
        float v2 = oacc[nt][2] * inv1, v3 = oacc[nt][3] * inv1;
        size_t o0 = (size_t)r0 * DM + c, o1 = (size_t)(r0 + 8) * DM + c;
        ((uint32_t*)Ch)[o0 >> 1] = packbf(v0, v1);
        ((uint32_t*)Ch)[o1 >> 1] = packbf(v2, v3);
        ((uint32_t*)Cl)[o0 >> 1] = packbf(lores(v0), lores(v1));
        ((uint32_t*)Cl)[o1 >> 1] = packbf(lores(v2), lores(v3));
    }
}

// ---------------------------------------------------------------------------
// Fused residual + LayerNorm (1024): out = LN(x+sub)*g + b, plus hi/lo split
// ---------------------------------------------------------------------------
__global__ __launch_bounds__(256)
void ln_k(const float* __restrict__ x, const float* __restrict__ sub,
          const float* __restrict__ g, const float* __restrict__ b,
          float* __restrict__ out, __nv_bfloat16* __restrict__ oh,
          __nv_bfloat16* __restrict__ ol)
{
    const int tid = threadIdx.x;
    const size_t base = (size_t)blockIdx.x * DM + tid * 4;

    float4 xv = *(const float4*)(x + base);
    float4 sv = *(const float4*)(sub + base);
    float v0 = xv.x + sv.x, v1 = xv.y + sv.y, v2 = xv.z + sv.z, v3 = xv.w + sv.w;

    __shared__ float red[256];
    red[tid] = v0 + v1 + v2 + v3; __syncthreads();
#pragma unroll
    for (int s = 128; s > 0; s >>= 1) {
        if (tid < s) red[tid] += red[tid + s];
        __syncthreads();
    }
    const float mu = red[0] * (1.f / DM);
    __syncthreads();

    const float d0 = v0 - mu, d1 = v1 - mu, d2 = v2 - mu, d3 = v3 - mu;
    red[tid] = d0*d0 + d1*d1 + d2*d2 + d3*d3; __syncthreads();
#pragma unroll
    for (int s = 128; s > 0; s >>= 1) {
        if (tid < s) red[tid] += red[tid + s];
        __syncthreads();
    }
    const float inv = rsqrtf(red[0] * (1.f / DM) + LN_EPS);

    float4 gv = *(const float4*)(g + tid * 4);
    float4 bv = *(const float4*)(b + tid * 4);
    float o0 = d0 * inv * gv.x + bv.x;
    float o1 = d1 * inv * gv.y + bv.y;
    float o2 = d2 * inv * gv.z + bv.z;
    float o3 = d3 * inv * gv.w + bv.w;
    *(float4*)(out + base) = make_float4(o0, o1, o2, o3);
    if (oh) {
        ((uint32_t*)oh)[base >> 1]       = packbf(o0, o1);
        ((uint32_t*)oh)[(base >> 1) + 1] = packbf(o2, o3);
        ((uint32_t*)ol)[base >> 1]       = packbf(lores(o0), lores(o1));
        ((uint32_t*)ol)[(base >> 1) + 1] = packbf(lores(o2), lores(o3));
    }
}

// ---------------------------------------------------------------------------
// Host launcher
// ---------------------------------------------------------------------------
extern "C" void kernel_launch(void* const* d_in, const int* in_sizes, int n_in,
                              void* d_out, int out_size)
{
    (void)in_sizes; (void)n_in; (void)out_size;

    const float* x_in = (const float*)d_in[0];
    const float* wq  = (const float*)d_in[1];
    const float* bq  = (const float*)d_in[2];
    const float* wk  = (const float*)d_in[3];
    const float* bk  = (const float*)d_in[4];
    const float* wv  = (const float*)d_in[5];
    const float* bv  = (const float*)d_in[6];
    const float* wo  = (const float*)d_in[7];
    const float* bo  = (const float*)d_in[8];
    const float* w1  = (const float*)d_in[9];
    const float* b1  = (const float*)d_in[10];
    const float* w2  = (const float*)d_in[11];
    const float* b2  = (const float*)d_in[12];
    const float* ln1g = (const float*)d_in[13];
    const float* ln1b = (const float*)d_in[14];
    const float* ln2g = (const float*)d_in[15];
    const float* ln2b = (const float*)d_in[16];

    static bool attr_done = false;
    if (!attr_done) {
        cudaFuncSetAttribute(gemm_h<0>, cudaFuncAttributeMaxDynamicSharedMemorySize, HSM_TOTAL);
        cudaFuncSetAttribute(gemm_h<1>, cudaFuncAttributeMaxDynamicSharedMemorySize, HSM_TOTAL);
        cudaFuncSetAttribute(flash_k,   cudaFuncAttributeMaxDynamicSharedMemorySize, FSM_TOTAL);
        attr_done = true;
    }

    float *x, *t, *bqkv;
    __nv_bfloat16 *wqkvh,*wqkvl,*woh,*wol,*w1h,*w1l,*w2h,*w2l;
    __nv_bfloat16 *xh,*xl,*qkvh,*qkvl,*cxh,*cxl,*hh,*hl;
    cudaGetSymbolAddress((void**)&x, g_x);
    cudaGetSymbolAddress((void**)&t, g_t);
    cudaGetSymbolAddress((void**)&bqkv, g_bqkv);
    cudaGetSymbolAddress((void**)&wqkvh, g_wqkvh); cudaGetSymbolAddress((void**)&wqkvl, g_wqkvl);
    cudaGetSymbolAddress((void**)&woh, g_woh);     cudaGetSymbolAddress((void**)&wol, g_wol);
    cudaGetSymbolAddress((void**)&w1h, g_w1h);     cudaGetSymbolAddress((void**)&w1l, g_w1l);
    cudaGetSymbolAddress((void**)&w2h, g_w2h);     cudaGetSymbolAddress((void**)&w2l, g_w2l);
    cudaGetSymbolAddress((void**)&xh, g_xh);       cudaGetSymbolAddress((void**)&xl, g_xl);
    cudaGetSymbolAddress((void**)&qkvh, g_qkvh);   cudaGetSymbolAddress((void**)&qkvl, g_qkvl);
    cudaGetSymbolAddress((void**)&cxh, g_cxh);     cudaGetSymbolAddress((void**)&cxl, g_cxl);
    cudaGetSymbolAddress((void**)&hh, g_hh);       cudaGetSymbolAddress((void**)&hl, g_hl);

    // ONE fused prep launch
    prep_k<<<(int)((PREP_T + 255) / 256), 256>>>(
        x_in, wq, wk, wv, bq, bk, bv, wo, w1, w2,
        x, xh, xl, wqkvh, wqkvl, bqkv, woh, wol, w1h, w1l, w2h, w2l);

    dim3 gQKV(3*DM / 64, SEQ / 128);    // 48 x 16 = 768 CTAs
    dim3 gP(DM / 64, SEQ / 128);        // 16 x 16 = 256 CTAs
    dim3 gF1(DFF / 64, SEQ / 128);      // 64 x 16 = 1024 CTAs
    dim3 gAtt(SEQ / 128, NH);

    for (int l = 0; l < NL; l++) {
        const __nv_bfloat16 *Wqkvh = wqkvh + (size_t)l*DM*3*DM, *Wqkvl = wqkvl + (size_t)l*DM*3*DM;
        const __nv_bfloat16 *Woh = woh + (size_t)l*DM*DM,  *Wol = wol + (size_t)l*DM*DM;
        const __nv_bfloat16 *W1h = w1h + (size_t)l*DM*DFF, *W1l = w1l + (size_t)l*DM*DFF;
        const __nv_bfloat16 *W2h = w2h + (size_t)l*DFF*DM, *W2l = w2l + (size_t)l*DFF*DM;
        const float *Bqkv = bqkv + (size_t)l*3*DM;
        const float *Bo = bo + (size_t)l*DM;
        const float *B1 = b1 + (size_t)l*DFF, *B2 = b2 + (size_t)l*DM;
        const float *G1 = ln1g + (size_t)l*DM, *Be1 = ln1b + (size_t)l*DM;
        const float *G2 = ln2g + (size_t)l*DM, *Be2 = ln2b + (size_t)l*DM;

        // fused QKV projection: [SEQ,1024] @ [1024,3072] -> qkv hi/lo
        gemm_h<0><<<gQKV,128,HSM_TOTAL>>>(xh, xl, Wqkvh, Wqkvl, Bqkv,
                                          nullptr, qkvh, qkvl, 3*DM, DM);
        // fused attention (Q at col 0, K at col DM, V at col 2*DM of qkv)
        flash_k<<<gAtt,256,FSM_TOTAL>>>(qkvh, qkvl, qkvh + DM, qkvl + DM,
                                        qkvh + 2*DM, qkvl + 2*DM, cxh, cxl, 3*DM);
        // attn_out = ctx @ Wo + bo (fp32)
        gemm_h<0><<<gP,128,HSM_TOTAL>>>(cxh, cxl, Woh, Wol, Bo, t, nullptr, nullptr, DM, DM);
        // x = LN1(x + attn_out), also split
        ln_k<<<SEQ,256>>>(x, t, G1, Be1, x, xh, xl);
        // h = gelu(x @ W1 + b1) -> hi/lo
        gemm_h<1><<<gF1,128,HSM_TOTAL>>>(xh, xl, W1h, W1l, B1, nullptr, hh, hl, DFF, DM);
        // ffn_out = h @ W2 + b2 (fp32)
        gemm_h<0><<<gP,128,HSM_TOTAL>>>(hh, hl, W2h, W2l, B2, t, nullptr, nullptr, DM, DFF);
        // x = LN2(x + ffn_out); final layer -> d_out
        float* outp = (l == NL - 1) ? (float*)d_out : x;
        __nv_bfloat16* oh = (l == NL - 1) ? nullptr : xh;
        __nv_bfloat16* ol = (l == NL - 1) ? nullptr : xl;
        ln_k<<<SEQ,256>>>(x, t, G2, Be2, outp, oh, ol);
    }
}

// round 15
// speedup vs baseline: 1.0298x; 1.0218x over previous
#include <cuda_runtime.h>
#include <cuda_bf16.h>
#include <math.h>
#include <stdint.h>

// Problem constants
#define SEQ   2048
#define DM    1024
#define NH    16
#define DK    64
#define DFF   4096
#define NL    4
#define LN_EPS 1e-5f

// ---------------------------------------------------------------------------
// Scratch (static device globals: allocation-free kernel_launch)
// ---------------------------------------------------------------------------
__device__ __nv_bfloat16 g_wqkvh[(size_t)NL*DM*3*DM], g_wqkvl[(size_t)NL*DM*3*DM];
__device__ float         g_bqkv[NL*3*DM];
__device__ __nv_bfloat16 g_woh[NL*DM*DM],  g_wol[NL*DM*DM];
__device__ __nv_bfloat16 g_w1h[NL*DM*DFF], g_w1l[NL*DM*DFF];
__device__ __nv_bfloat16 g_w2h[NL*DFF*DM], g_w2l[NL*DFF*DM];
__device__ float g_x[SEQ*DM];
__device__ float g_t[SEQ*DM];
__device__ __nv_bfloat16 g_xh[SEQ*DM],  g_xl[SEQ*DM];
__device__ __nv_bfloat16 g_qkvh[(size_t)SEQ*3*DM], g_qkvl[(size_t)SEQ*3*DM];
__device__ __nv_bfloat16 g_cxh[SEQ*DM], g_cxl[SEQ*DM];
__device__ __nv_bfloat16 g_hh[SEQ*DFF], g_hl[SEQ*DFF];

// ---------------------------------------------------------------------------
// Helpers
// ---------------------------------------------------------------------------
__device__ __forceinline__ uint32_t smem_u32(const void* p) {
    return (uint32_t)__cvta_generic_to_shared(p);
}
__device__ __forceinline__ uint32_t packbf(float a, float b) {
    __nv_bfloat162 t = __floats2bfloat162_rn(a, b);
    return *reinterpret_cast<uint32_t*>(&t);
}
__device__ __forceinline__ float lores(float a) {
    return a - __bfloat162float(__float2bfloat16_rn(a));
}
__device__ __forceinline__ void cp16(uint32_t dst, const void* src) {
    asm volatile("cp.async.cg.shared.global [%0], [%1], 16;\n" :: "r"(dst), "l"(src));
}
__device__ __forceinline__ void cp_commit() {
    asm volatile("cp.async.commit_group;\n" ::);
}
template<int N>
__device__ __forceinline__ void cp_wait() {
    asm volatile("cp.async.wait_group %0;\n" :: "n"(N));
}
__device__ __forceinline__ void ldsm_x4(uint32_t* r, uint32_t addr) {
    asm volatile("ldmatrix.sync.aligned.m8n8.x4.shared.b16 {%0,%1,%2,%3}, [%4];\n"
                 : "=r"(r[0]), "=r"(r[1]), "=r"(r[2]), "=r"(r[3]) : "r"(addr));
}
__device__ __forceinline__ void ldsm_x4_t(uint32_t* r, uint32_t addr) {
    asm volatile("ldmatrix.sync.aligned.m8n8.x4.trans.shared.b16 {%0,%1,%2,%3}, [%4];\n"
                 : "=r"(r[0]), "=r"(r[1]), "=r"(r[2]), "=r"(r[3]) : "r"(addr));
}
__device__ __forceinline__ void mma_bf16(float* c, const uint32_t* a, const uint32_t* b) {
    asm volatile(
        "mma.sync.aligned.m16n8k16.row.col.f32.bf16.bf16.f32 "
        "{%0,%1,%2,%3}, {%4,%5,%6,%7}, {%8,%9}, {%0,%1,%2,%3};\n"
        : "+f"(c[0]), "+f"(c[1]), "+f"(c[2]), "+f"(c[3])
        : "r"(a[0]), "r"(a[1]), "r"(a[2]), "r"(a[3]), "r"(b[0]), "r"(b[1]));
}

// ---------------------------------------------------------------------------
// ONE fused prep kernel: x copy+split, QKV weight pack, QKV bias pack,
// Wo/W1/W2 splits.
// ---------------------------------------------------------------------------
#define N4_X    (SEQ*DM/4)
#define N4_QKV  ((size_t)NL*DM*3*DM/4)
#define N4_WO   (NL*DM*DM/4)
#define N4_W1   ((size_t)NL*DM*DFF/4)
#define N4_W2   N4_W1
#define N4_BQ   (NL*3*DM/4)
#define PREP_T  ((size_t)N4_X + N4_QKV + N4_WO + N4_W1 + N4_W2 + N4_BQ)

__global__ __launch_bounds__(256)
void prep_k(const float* __restrict__ x_in,
            const float* __restrict__ wq, const float* __restrict__ wk,
            const float* __restrict__ wv, const float* __restrict__ bq,
            const float* __restrict__ bk, const float* __restrict__ bv,
            const float* __restrict__ wo, const float* __restrict__ w1,
            const float* __restrict__ w2,
            float* __restrict__ xo, __nv_bfloat16* __restrict__ xh,
            __nv_bfloat16* __restrict__ xl,
            __nv_bfloat16* __restrict__ qkvH, __nv_bfloat16* __restrict__ qkvL,
            float* __restrict__ bqkv,
            __nv_bfloat16* __restrict__ woh, __nv_bfloat16* __restrict__ wol,
            __nv_bfloat16* __restrict__ w1h, __nv_bfloat16* __restrict__ w1l,
            __nv_bfloat16* __restrict__ w2h, __nv_bfloat16* __restrict__ w2l)
{
    size_t i = (size_t)blockIdx.x * 256 + threadIdx.x;
    if (i >= PREP_T) return;

    auto splitStore = [](float4 v, __nv_bfloat16* H, __nv_bfloat16* L, size_t i4) {
        ((uint32_t*)H)[i4*2]   = packbf(v.x, v.y);
        ((uint32_t*)H)[i4*2+1] = packbf(v.z, v.w);
        ((uint32_t*)L)[i4*2]   = packbf(lores(v.x), lores(v.y));
        ((uint32_t*)L)[i4*2+1] = packbf(lores(v.z), lores(v.w));
    };

    if (i < N4_X) {
        float4 v = ((const float4*)x_in)[i];
        ((float4*)xo)[i] = v;
        splitStore(v, xh, xl, i);
        return;
    }
    i -= N4_X;
    if (i < N4_QKV) {
        size_t e = i * 4;
        int j = (int)(e % (3 * DM));
        size_t rowl = e / (3 * DM);
        int s = j / DM, c = j % DM;
        const float* src = (s == 0) ? wq : ((s == 1) ? wk : wv);
        float4 v = *(const float4*)&src[rowl * DM + c];
        splitStore(v, qkvH, qkvL, i);
        return;
    }
    i -= N4_QKV;
    if (i < N4_WO) {
        splitStore(((const float4*)wo)[i], woh, wol, i);
        return;
    }
    i -= N4_WO;
    if (i < N4_W1) {
        splitStore(((const float4*)w1)[i], w1h, w1l, i);
        return;
    }
    i -= N4_W1;
    if (i < N4_W2) {
        splitStore(((const float4*)w2)[i], w2h, w2l, i);
        return;
    }
    i -= N4_W2;
    {
        size_t e = i * 4;
        int l = (int)(e / (3 * DM)), j = (int)(e % (3 * DM));
        int s = j / DM, c = j % DM;
        const float* src = (s == 0) ? bq : ((s == 1) ? bk : bv);
        ((float4*)bqkv)[i] = *(const float4*)&src[l * DM + c];
    }
}

// ---------------------------------------------------------------------------
// GEMM (pipelined fragments): 256 threads, tile 128x128x32, warp tile 64x32,
// 4-stage cp.async, ONE sync/kt. Key change vs prior rounds: ALL ldmatrix
// fragment loads for the kt (both k16 chunks, 96 regs) are issued BEFORE the
// 96 MMAs, so the scoreboard overlaps chunk-1 loads with chunk-0 MMAs and the
// per-chunk ldsm->mma dependency bubble is paid once per kt, not twice.
// Addressing is strength-reduced (per-thread base offsets computed once).
// smem strides: A rows 40 elems (80B), B rows 136 elems (272B).
// ---------------------------------------------------------------------------
#define GSM_STAGE 37888
#define GSM_TOTAL (4 * GSM_STAGE)

template<int ACT>
__global__ __launch_bounds__(256, 1)
void gemm_s(const __nv_bfloat16* __restrict__ Ahg, const __nv_bfloat16* __restrict__ Alg,
            const __nv_bfloat16* __restrict__ Bhg, const __nv_bfloat16* __restrict__ Blg,
            const float* __restrict__ bias,
            float* __restrict__ Cf, __nv_bfloat16* __restrict__ Ch,
            __nv_bfloat16* __restrict__ Cl, int N, int K)
{
    extern __shared__ char smem[];
    const int tid = threadIdx.x, lane = tid & 31, warp = tid >> 5;
    const int wm0 = (warp & 1) * 64, wn0 = (warp >> 1) * 32;
    const int bm0 = blockIdx.y * 128, bn0 = blockIdx.x * 128;

    // per-thread constant load offsets (strength-reduced addressing)
    const size_t aOff = (size_t)(bm0 + (tid >> 2)) * K + (tid & 3) * 8;
    const size_t bOff = (size_t)(tid >> 4) * N + bn0 + (tid & 15) * 8;
    const uint32_t sA = smem_u32(smem) + ((tid >> 2) * 40 + (tid & 3) * 8) * 2;
    const uint32_t sB = smem_u32(smem) + 20480 + ((tid >> 4) * 136 + (tid & 15) * 8) * 2;

    auto load_stage = [&](int s, int kt) {
        const uint32_t st = s * GSM_STAGE;
        const size_t ka = aOff + kt * 32;
        const size_t kb = bOff + (size_t)kt * 32 * N;
#pragma unroll
        for (int p = 0; p < 2; p++) {
            cp16(sA + st + p * (64*40*2),          Ahg + ka + (size_t)p * 64 * K);
            cp16(sA + st + 10240 + p * (64*40*2),  Alg + ka + (size_t)p * 64 * K);
        }
#pragma unroll
        for (int p = 0; p < 2; p++) {
            cp16(sB + st + p * (16*136*2),         Bhg + kb + (size_t)p * 16 * N);
            cp16(sB + st + 8704 + p * (16*136*2),  Blg + kb + (size_t)p * 16 * N);
        }
    };

    // per-thread ldmatrix source addresses (constant across kt except stage)
    const uint32_t base = smem_u32(smem);
    const uint32_t aRow = (wm0 + (lane & 15)) * 40 + ((lane >> 4) << 3);
    const int g = lane >> 3;
    const uint32_t bRow = ((lane & 7) + ((g & 1) << 3)) * 136 + wn0 + ((g >> 1) << 3);

    float acc[4][4][4];
#pragma unroll
    for (int i = 0; i < 4; i++)
#pragma unroll
        for (int j = 0; j < 4; j++)
#pragma unroll
            for (int q = 0; q < 4; q++) acc[i][j][q] = 0.f;

    const int KT = K / 32;
    load_stage(0, 0); cp_commit();
    load_stage(1, 1); cp_commit();
    load_stage(2, 2); cp_commit();

    for (int kt = 0; kt < KT; kt++) {
        cp_wait<2>();
        __syncthreads();

        if (kt + 3 < KT) load_stage((kt + 3) & 3, kt + 3);
        cp_commit();

        const uint32_t st = base + (kt & 3) * GSM_STAGE;
        const uint32_t ah = st + aRow * 2;
        const uint32_t al = ah + 10240;
        const uint32_t bh = st + 20480 + bRow * 2;
        const uint32_t bl = bh + 8704;

        // ---- load ALL fragments for this kt (both k16 chunks) up front
        uint32_t aH[2][4][4], aL[2][4][4];
        uint32_t bH[2][4][2], bL[2][4][2];
#pragma unroll
        for (int kc = 0; kc < 2; kc++) {
            const uint32_t ko = kc * 32;   // 16 elems * 2B
#pragma unroll
            for (int mt = 0; mt < 4; mt++) {
                ldsm_x4(aH[kc][mt], ah + mt * (16*40*2) + ko);
                ldsm_x4(aL[kc][mt], al + mt * (16*40*2) + ko);
            }
#pragma unroll
            for (int np = 0; np < 2; np++) {
                uint32_t t4[4];
                ldsm_x4_t(t4, bh + kc * (16*136*2) + np * 32);
                bH[kc][2*np][0] = t4[0]; bH[kc][2*np][1] = t4[1];
                bH[kc][2*np+1][0] = t4[2]; bH[kc][2*np+1][1] = t4[3];
                ldsm_x4_t(t4, bl + kc * (16*136*2) + np * 32);
                bL[kc][2*np][0] = t4[0]; bL[kc][2*np][1] = t4[1];
                bL[kc][2*np+1][0] = t4[2]; bL[kc][2*np+1][1] = t4[3];
            }
        }

        // ---- all 96 MMAs
#pragma unroll
        for (int kc = 0; kc < 2; kc++) {
#pragma unroll
            for (int mt = 0; mt < 4; mt++)
#pragma unroll
                for (int nt = 0; nt < 4; nt++)
                    mma_bf16(acc[mt][nt], aH[kc][mt], bH[kc][nt]);
#pragma unroll
            for (int mt = 0; mt < 4; mt++)
#pragma unroll
                for (int nt = 0; nt < 4; nt++)
                    mma_bf16(acc[mt][nt], aL[kc][mt], bH[kc][nt]);
#pragma unroll
            for (int mt = 0; mt < 4; mt++)
#pragma unroll
                for (int nt = 0; nt < 4; nt++)
                    mma_bf16(acc[mt][nt], aH[kc][mt], bL[kc][nt]);
        }
    }

    // ---- epilogue
#pragma unroll
    for (int mt = 0; mt < 4; mt++) {
        int r0 = bm0 + wm0 + mt * 16 + (lane >> 2);
#pragma unroll
        for (int nt = 0; nt < 4; nt++) {
            int c = bn0 + wn0 + nt * 8 + (lane & 3) * 2;
            float b0 = bias[c], b1 = bias[c + 1];
            float v[4];
#pragma unroll
            for (int q = 0; q < 4; q++) {
                float x = acc[mt][nt][q] + ((q & 1) ? b1 : b0);
                if (ACT == 1) {
                    float tt = tanhf(0.7978845608028654f * (x + 0.044715f * x * x * x));
                    x = 0.5f * x * (1.f + tt);
                }
                v[q] = x;
            }
            size_t o0 = (size_t)r0 * N + c, o1 = (size_t)(r0 + 8) * N + c;
            if (Cf) {
                *(float2*)&Cf[o0] = make_float2(v[0], v[1]);
                *(float2*)&Cf[o1] = make_float2(v[2], v[3]);
            }
            if (Ch) {
                ((uint32_t*)Ch)[o0 >> 1] = packbf(v[0], v[1]);
                ((uint32_t*)Ch)[o1 >> 1] = packbf(v[2], v[3]);
                ((uint32_t*)Cl)[o0 >> 1] = packbf(lores(v[0]), lores(v[1]));
                ((uint32_t*)Cl)[o1 >> 1] = packbf(lores(v[2]), lores(v[3]));
            }
        }
    }
}

// ---------------------------------------------------------------------------
// Flash attention: per block = (q-block of 128 rows, head). Packed QKV input.
// ---------------------------------------------------------------------------
#define FSM_ARR   18432
#define FSM_KV0   (2 * FSM_ARR)
#define FSM_STAGE (4 * FSM_ARR)
#define FSM_TOTAL (FSM_KV0 + 2 * FSM_STAGE)

__global__ __launch_bounds__(256, 1)
void flash_k(const __nv_bfloat16* __restrict__ Qh, const __nv_bfloat16* __restrict__ Ql,
             const __nv_bfloat16* __restrict__ Kh, const __nv_bfloat16* __restrict__ Kl,
             const __nv_bfloat16* __restrict__ Vh, const __nv_bfloat16* __restrict__ Vl,
             __nv_bfloat16* __restrict__ Ch, __nv_bfloat16* __restrict__ Cl, int ldq)
{
    extern __shared__ char smem[];
    const int tid = threadIdx.x, lane = tid & 31, warp = tid >> 5;
    const int qb = blockIdx.x, head = blockIdx.y;
    const int col0 = head * DK;

    __nv_bfloat16* Qsh = (__nv_bfloat16*)smem;
    __nv_bfloat16* Qsl = (__nv_bfloat16*)(smem + FSM_ARR);
    auto Ksh = [&](int s){ return (__nv_bfloat16*)(smem + FSM_KV0 + s*FSM_STAGE); };
    auto Ksl = [&](int s){ return (__nv_bfloat16*)(smem + FSM_KV0 + s*FSM_STAGE + FSM_ARR); };
    auto Vsh = [&](int s){ return (__nv_bfloat16*)(smem + FSM_KV0 + s*FSM_STAGE + 2*FSM_ARR); };
    auto Vsl = [&](int s){ return (__nv_bfloat16*)(smem + FSM_KV0 + s*FSM_STAGE + 3*FSM_ARR); };

#pragma unroll
    for (int p = 0; p < 4; p++) {
        int c = p * 256 + tid;
        int r = c >> 3, sg = c & 7;
        size_t go = (size_t)(qb * 128 + r) * ldq + col0 + sg * 8;
        cp16(smem_u32(Qsh + r*72 + sg*8), Qh + go);
        cp16(smem_u32(Qsl + r*72 + sg*8), Ql + go);
    }
    auto load_kv = [&](int s, int t) {
#pragma unroll
        for (int p = 0; p < 4; p++) {
            int c = p * 256 + tid;
            int r = c >> 3, sg = c & 7;
            size_t go = (size_t)(t * 128 + r) * ldq + col0 + sg * 8;
            cp16(smem_u32(Ksh(s) + r*72 + sg*8), Kh + go);
            cp16(smem_u32(Ksl(s) + r*72 + sg*8), Kl + go);
            cp16(smem_u32(Vsh(s) + r*72 + sg*8), Vh + go);
            cp16(smem_u32(Vsl(s) + r*72 + sg*8), Vl + go);
        }
    };
    load_kv(0, 0);
    cp_commit();

    float oacc[8][4];
#pragma unroll
    for (int i = 0; i < 8; i++)
#pragma unroll
        for (int q = 0; q < 4; q++) oacc[i][q] = 0.f;
    float mrun[2] = {-INFINITY, -INFINITY};
    float lrun[2] = {0.f, 0.f};

    const int NT_KV = SEQ / 128;
    for (int t = 0; t < NT_KV; t++) {
        if (t + 1 < NT_KV) load_kv((t + 1) & 1, t + 1);
        cp_commit();
        cp_wait<1>();
        __syncthreads();

        const int s = t & 1;
        const __nv_bfloat16 *ksh = Ksh(s), *ksl = Ksl(s), *vsh = Vsh(s), *vsl = Vsl(s);

        float sacc[16][4];
#pragma unroll
        for (int i = 0; i < 16; i++)
#pragma unroll
            for (int q = 0; q < 4; q++) sacc[i][q] = 0.f;

#pragma unroll
        for (int kc = 0; kc < 4; kc++) {
            const int kb = kc * 16;
            uint32_t aH[4], aL[4];
            {
                int row = warp * 16 + (lane & 15);
                int ko  = kb + ((lane >> 4) << 3);
                ldsm_x4(aH, smem_u32(Qsh + row*72 + ko));
                ldsm_x4(aL, smem_u32(Qsl + row*72 + ko));
            }
#pragma unroll
            for (int np = 0; np < 8; np++) {
                int nrow = np * 16 + (lane & 7) + ((lane >> 4) << 3);
                int kbase = kb + (((lane >> 3) & 1) << 3);
                uint32_t bh4[4], bl4[4];
                ldsm_x4(bh4, smem_u32(ksh + nrow*72 + kbase));
                ldsm_x4(bl4, smem_u32(ksl + nrow*72 + kbase));
                mma_bf16(sacc[2*np],   aH, bh4);
                mma_bf16(sacc[2*np],   aL, bh4);
                mma_bf16(sacc[2*np],   aH, bl4);
                mma_bf16(sacc[2*np+1], aH, bh4 + 2);
                mma_bf16(sacc[2*np+1], aL, bh4 + 2);
                mma_bf16(sacc[2*np+1], aH, bl4 + 2);
            }
        }

        float mnew[2];
#pragma unroll
        for (int rr = 0; rr < 2; rr++) {
            float m = -INFINITY;
#pragma unroll
            for (int nt = 0; nt < 16; nt++) {
                sacc[nt][2*rr]   *= 0.125f;
                sacc[nt][2*rr+1] *= 0.125f;
                m = fmaxf(m, fmaxf(sacc[nt][2*rr], sacc[nt][2*rr+1]));
            }
            m = fmaxf(m, __shfl_xor_sync(0xffffffffu, m, 1));
            m = fmaxf(m, __shfl_xor_sync(0xffffffffu, m, 2));
            mnew[rr] = fmaxf(mrun[rr], m);
        }
        float sc0 = __expf(mrun[0] - mnew[0]);
        float sc1 = __expf(mrun[1] - mnew[1]);
        float ls0 = 0.f, ls1 = 0.f;
#pragma unroll
        for (int nt = 0; nt < 16; nt++) {
            float p0 = __expf(sacc[nt][0] - mnew[0]);
            float p1 = __expf(sacc[nt][1] - mnew[0]);
            float p2 = __expf(sacc[nt][2] - mnew[1]);
            float p3 = __expf(sacc[nt][3] - mnew[1]);
            sacc[nt][0] = p0; sacc[nt][1] = p1; sacc[nt][2] = p2; sacc[nt][3] = p3;
            ls0 += p0 + p1; ls1 += p2 + p3;
        }
        ls0 += __shfl_xor_sync(0xffffffffu, ls0, 1);
        ls0 += __shfl_xor_sync(0xffffffffu, ls0, 2);
        ls1 += __shfl_xor_sync(0xffffffffu, ls1, 1);
        ls1 += __shfl_xor_sync(0xffffffffu, ls1, 2);
        lrun[0] = lrun[0] * sc0 + ls0;
        lrun[1] = lrun[1] * sc1 + ls1;
        mrun[0] = mnew[0]; mrun[1] = mnew[1];
#pragma unroll
        for (int nt = 0; nt < 8; nt++) {
            oacc[nt][0] *= sc0; oacc[nt][1] *= sc0;
            oacc[nt][2] *= sc1; oacc[nt][3] *= sc1;
        }

#pragma unroll
        for (int kt = 0; kt < 8; kt++) {
            uint32_t pH[4], pL[4];
            pH[0] = packbf(sacc[2*kt][0],   sacc[2*kt][1]);
            pH[1] = packbf(sacc[2*kt][2],   sacc[2*kt][3]);
            pH[2] = packbf(sacc[2*kt+1][0], sacc[2*kt+1][1]);
            pH[3] = packbf(sacc[2*kt+1][2], sacc[2*kt+1][3]);
            pL[0] = packbf(lores(sacc[2*kt][0]),   lores(sacc[2*kt][1]));
            pL[1] = packbf(lores(sacc[2*kt][2]),   lores(sacc[2*kt][3]));
            pL[2] = packbf(lores(sacc[2*kt+1][0]), lores(sacc[2*kt+1][1]));
            pL[3] = packbf(lores(sacc[2*kt+1][2]), lores(sacc[2*kt+1][3]));
#pragma unroll
            for (int np = 0; np < 4; np++) {
                int g  = lane >> 3;
                int rk = kt * 16 + (lane & 7) + ((g & 1) << 3);
                int nc = np * 16 + ((g >> 1) << 3);
                uint32_t bh4[4], bl4[4];
                ldsm_x4_t(bh4, smem_u32(vsh + rk*72 + nc));
                ldsm_x4_t(bl4, smem_u32(vsl + rk*72 + nc));
                mma_bf16(oacc[2*np],   pH, bh4);
                mma_bf16(oacc[2*np],   pL, bh4);
                mma_bf16(oacc[2*np],   pH, bl4);
                mma_bf16(oacc[2*np+1], pH, bh4 + 2);
                mma_bf16(oacc[2*np+1], pL, bh4 + 2);
                mma_bf16(oacc[2*np+1], pH, bl4 + 2);
            }
        }
        __syncthreads();
    }

    float inv0 = 1.f / lrun[0], inv1 = 1.f / lrun[1];
    int r0 = qb * 128 + warp * 16 + (lane >> 2);
#pragma unroll
    for (int nt = 0; nt < 8; nt++) {
        int c = col0 + nt * 8 + (lane & 3) * 2;
        float v0 = oacc[nt][0] * inv0, v1 = oacc[nt][1] * inv0;
        float v2 = oacc[nt][2] * inv1, v3 = oacc[nt][3] * inv1;
        size_t o0 = (size_t)r0 * DM + c, o1 = (size_t)(r0 + 8) * DM + c;
        ((uint32_t*)Ch)[o0 >> 1] = packbf(v0, v1);
        ((uint32_t*)Ch)[o1 >> 1] = packbf(v2, v3);
        ((uint32_t*)Cl)[o0 >> 1] = packbf(lores(v0), lores(v1));
        ((uint32_t*)Cl)[o1 >> 1] = packbf(lores(v2), lores(v3));
    }
}

// ---------------------------------------------------------------------------
// Fused residual + LayerNorm (1024): out = LN(x+sub)*g + b, plus hi/lo split
// ---------------------------------------------------------------------------
__global__ __launch_bounds__(256)
void ln_k(const float* __restrict__ x, const float* __restrict__ sub,
          const float* __restrict__ g, const float* __restrict__ b,
          float* __restrict__ out, __nv_bfloat16* __restrict__ oh,
          __nv_bfloat16* __restrict__ ol)
{
    const int tid = threadIdx.x;
    const size_t base = (size_t)blockIdx.x * DM + tid * 4;

    float4 xv = *(const float4*)(x + base);
    float4 sv = *(const float4*)(sub + base);
    float v0 = xv.x + sv.x, v1 = xv.y + sv.y, v2 = xv.z + sv.z, v3 = xv.w + sv.w;

    __shared__ float red[256];
    red[tid] = v0 + v1 + v2 + v3; __syncthreads();
#pragma unroll
    for (int s = 128; s > 0; s >>= 1) {
        if (tid < s) red[tid] += red[tid + s];
        __syncthreads();
    }
    const float mu = red[0] * (1.f / DM);
    __syncthreads();

    const float d0 = v0 - mu, d1 = v1 - mu, d2 = v2 - mu, d3 = v3 - mu;
    red[tid] = d0*d0 + d1*d1 + d2*d2 + d3*d3; __syncthreads();
#pragma unroll
    for (int s = 128; s > 0; s >>= 1) {
        if (tid < s) red[tid] += red[tid + s];
        __syncthreads();
    }
    const float inv = rsqrtf(red[0] * (1.f / DM) + LN_EPS);

    float4 gv = *(const float4*)(g + tid * 4);
    float4 bv = *(const float4*)(b + tid * 4);
    float o0 = d0 * inv * gv.x + bv.x;
    float o1 = d1 * inv * gv.y + bv.y;
    float o2 = d2 * inv * gv.z + bv.z;
    float o3 = d3 * inv * gv.w + bv.w;
    *(float4*)(out + base) = make_float4(o0, o1, o2, o3);
    if (oh) {
        ((uint32_t*)oh)[base >> 1]       = packbf(o0, o1);
        ((uint32_t*)oh)[(base >> 1) + 1] = packbf(o2, o3);
        ((uint32_t*)ol)[base >> 1]       = packbf(lores(o0), lores(o1));
        ((uint32_t*)ol)[(base >> 1) + 1] = packbf(lores(o2), lores(o3));
    }
}

// ---------------------------------------------------------------------------
// Host launcher
// ---------------------------------------------------------------------------
extern "C" void kernel_launch(void* const* d_in, const int* in_sizes, int n_in,
                              void* d_out, int out_size)
{
    (void)in_sizes; (void)n_in; (void)out_size;

    const float* x_in = (const float*)d_in[0];
    const float* wq  = (const float*)d_in[1];
    const float* bq  = (const float*)d_in[2];
    const float* wk  = (const float*)d_in[3];
    const float* bk  = (const float*)d_in[4];
    const float* wv  = (const float*)d_in[5];
    const float* bv  = (const float*)d_in[6];
    const float* wo  = (const float*)d_in[7];
    const float* bo  = (const float*)d_in[8];
    const float* w1  = (const float*)d_in[9];
    const float* b1  = (const float*)d_in[10];
    const float* w2  = (const float*)d_in[11];
    const float* b2  = (const float*)d_in[12];
    const float* ln1g = (const float*)d_in[13];
    const float* ln1b = (const float*)d_in[14];
    const float* ln2g = (const float*)d_in[15];
    const float* ln2b = (const float*)d_in[16];

    static bool attr_done = false;
    if (!attr_done) {
        cudaFuncSetAttribute(gemm_s<0>, cudaFuncAttributeMaxDynamicSharedMemorySize, GSM_TOTAL);
        cudaFuncSetAttribute(gemm_s<1>, cudaFuncAttributeMaxDynamicSharedMemorySize, GSM_TOTAL);
        cudaFuncSetAttribute(flash_k,   cudaFuncAttributeMaxDynamicSharedMemorySize, FSM_TOTAL);
        attr_done = true;
    }

    float *x, *t, *bqkv;
    __nv_bfloat16 *wqkvh,*wqkvl,*woh,*wol,*w1h,*w1l,*w2h,*w2l;
    __nv_bfloat16 *xh,*xl,*qkvh,*qkvl,*cxh,*cxl,*hh,*hl;
    cudaGetSymbolAddress((void**)&x, g_x);
    cudaGetSymbolAddress((void**)&t, g_t);
    cudaGetSymbolAddress((void**)&bqkv, g_bqkv);
    cudaGetSymbolAddress((void**)&wqkvh, g_wqkvh); cudaGetSymbolAddress((void**)&wqkvl, g_wqkvl);
    cudaGetSymbolAddress((void**)&woh, g_woh);     cudaGetSymbolAddress((void**)&wol, g_wol);
    cudaGetSymbolAddress((void**)&w1h, g_w1h);     cudaGetSymbolAddress((void**)&w1l, g_w1l);
    cudaGetSymbolAddress((void**)&w2h, g_w2h);     cudaGetSymbolAddress((void**)&w2l, g_w2l);
    cudaGetSymbolAddress((void**)&xh, g_xh);       cudaGetSymbolAddress((void**)&xl, g_xl);
    cudaGetSymbolAddress((void**)&qkvh, g_qkvh);   cudaGetSymbolAddress((void**)&qkvl, g_qkvl);
    cudaGetSymbolAddress((void**)&cxh, g_cxh);     cudaGetSymbolAddress((void**)&cxl, g_cxl);
    cudaGetSymbolAddress((void**)&hh, g_hh);       cudaGetSymbolAddress((void**)&hl, g_hl);

    // ONE fused prep launch
    prep_k<<<(int)((PREP_T + 255) / 256), 256>>>(
        x_in, wq, wk, wv, bq, bk, bv, wo, w1, w2,
        x, xh, xl, wqkvh, wqkvl, bqkv, woh, wol, w1h, w1l, w2h, w2l);

    dim3 gQKV(3*DM / 128, SEQ / 128);   // 24 x 16 = 384 CTAs
    dim3 gP(DM / 128, SEQ / 128);       // 8 x 16 = 128 CTAs
    dim3 gF1(DFF / 128, SEQ / 128);     // 32 x 16 = 512 CTAs
    dim3 gAtt(SEQ / 128, NH);

    for (int l = 0; l < NL; l++) {
        const __nv_bfloat16 *Wqkvh = wqkvh + (size_t)l*DM*3*DM, *Wqkvl = wqkvl + (size_t)l*DM*3*DM;
        const __nv_bfloat16 *Woh = woh + (size_t)l*DM*DM,  *Wol = wol + (size_t)l*DM*DM;
        const __nv_bfloat16 *W1h = w1h + (size_t)l*DM*DFF, *W1l = w1l + (size_t)l*DM*DFF;
        const __nv_bfloat16 *W2h = w2h + (size_t)l*DFF*DM, *W2l = w2l + (size_t)l*DFF*DM;
        const float *Bqkv = bqkv + (size_t)l*3*DM;
        const float *Bo = bo + (size_t)l*DM;
        const float *B1 = b1 + (size_t)l*DFF, *B2 = b2 + (size_t)l*DM;
        const float *G1 = ln1g + (size_t)l*DM, *Be1 = ln1b + (size_t)l*DM;
        const float *G2 = ln2g + (size_t)l*DM, *Be2 = ln2b + (size_t)l*DM;

        // fused QKV projection: [SEQ,1024] @ [1024,3072] -> qkv hi/lo
        gemm_s<0><<<gQKV,256,GSM_TOTAL>>>(xh, xl, Wqkvh, Wqkvl, Bqkv,
                                          nullptr, qkvh, qkvl, 3*DM, DM);
        // fused attention (Q at col 0, K at col DM, V at col 2*DM of qkv)
        flash_k<<<gAtt,256,FSM_TOTAL>>>(qkvh, qkvl, qkvh + DM, qkvl + DM,
                                        qkvh + 2*DM, qkvl + 2*DM, cxh, cxl, 3*DM);
        // attn_out = ctx @ Wo + bo (fp32)
        gemm_s<0><<<gP,256,GSM_TOTAL>>>(cxh, cxl, Woh, Wol, Bo, t, nullptr, nullptr, DM, DM);
        // x = LN1(x + attn_out), also split
        ln_k<<<SEQ,256>>>(x, t, G1, Be1, x, xh, xl);
        // h = gelu(x @ W1 + b1) -> hi/lo
        gemm_s<1><<<gF1,256,GSM_TOTAL>>>(xh, xl, W1h, W1l, B1, nullptr, hh, hl, DFF, DM);
        // ffn_out = h @ W2 + b2 (fp32)
        gemm_s<0><<<gP,256,GSM_TOTAL>>>(hh, hl, W2h, W2l, B2, t, nullptr, nullptr, DM, DFF);
        // x = LN2(x + ffn_out); final layer -> d_out
        float* outp = (l == NL - 1) ? (float*)d_out : x;
        __nv_bfloat16* oh = (l == NL - 1) ? nullptr : xh;
        __nv_bfloat16* ol = (l == NL - 1) ? nullptr : xl;
        ln_k<<<SEQ,256>>>(x, t, G2, Be2, outp, oh, ol);
    }
}